// round 2
// baseline (speedup 1.0000x reference)
#include <cuda_runtime.h>
#include <math.h>

// Problem constants (fixed by the dataset problem)
#define NEXP   16
#define DIM    1024
#define FDIM   4096
#define SHDIM  2048
#define MAXT   8192
#define NSORT  8192      // next pow2 >= T
#define MAXCAP 1024

// ---------------- scratch (static __device__ globals; no allocations) -------
__device__ float g_scoresT[NEXP * MAXT];                         // [E][T]
__device__ int   g_ids[NEXP * MAXCAP];                           // [E][cap]
__device__ float g_tscore[NEXP * MAXCAP];                        // [E][cap]
__device__ float g_act[(size_t)NEXP * MAXCAP * FDIM];            // 256 MB
__device__ float g_shact[(size_t)MAXT * SHDIM];                  // 64 MB

__device__ __forceinline__ float sigmoidf_(float x) { return 1.f / (1.f + expf(-x)); }
__device__ __forceinline__ float siluf_(float x)    { return x   / (1.f + expf(-x)); }

// ---------------- gate: scores[e][t] = sigmoid(h[t] . gate_w[e]) ------------
__global__ void gate_kernel(const float* __restrict__ h,
                            const float* __restrict__ gate_w,
                            float* __restrict__ scoresT, int T) {
    int warp = (int)((blockIdx.x * blockDim.x + threadIdx.x) >> 5);
    int lane = threadIdx.x & 31;
    if (warp >= T) return;
    const float* hr = h + (size_t)warp * DIM;
    float hreg[32];
#pragma unroll
    for (int i = 0; i < 32; i++) hreg[i] = hr[lane + 32 * i];
#pragma unroll
    for (int e = 0; e < NEXP; e++) {
        const float* w = gate_w + e * DIM;
        float s = 0.f;
#pragma unroll
        for (int i = 0; i < 32; i++) s = fmaf(hreg[i], w[lane + 32 * i], s);
#pragma unroll
        for (int o = 16; o; o >>= 1) s += __shfl_xor_sync(0xffffffffu, s, o);
        if (lane == 0) scoresT[e * T + warp] = sigmoidf_(s);
    }
}

// ---------------- top-k per expert: exact, stable like jax.lax.top_k --------
// 64-bit key: (ordered score bits << 32) | (0xFFFFFFFF - idx); descending sort
// gives score-desc, idx-asc tie-break — identical selection to top_k.
__global__ void topk_kernel(const float* __restrict__ scoresT,
                            int* __restrict__ ids, float* __restrict__ tscore,
                            int T, int cap) {
    extern __shared__ unsigned long long s_keys[];
    int e = blockIdx.x;
    const float* s = scoresT + (size_t)e * T;
    for (int i = threadIdx.x; i < NSORT; i += blockDim.x) {
        float v = (i < T) ? s[i] : -1e30f;
        unsigned u  = __float_as_uint(v);
        unsigned ob = (u & 0x80000000u) ? ~u : (u | 0x80000000u);
        s_keys[i] = ((unsigned long long)ob << 32) | (unsigned)(0xFFFFFFFFu - (unsigned)i);
    }
    __syncthreads();
    for (unsigned k = 2; k <= NSORT; k <<= 1) {
        for (unsigned j = k >> 1; j > 0; j >>= 1) {
            for (unsigned i = threadIdx.x; i < NSORT; i += blockDim.x) {
                unsigned ixj = i ^ j;
                if (ixj > i) {
                    unsigned long long a = s_keys[i], b = s_keys[ixj];
                    bool up = ((i & k) == 0);
                    bool sw = up ? (a < b) : (a > b);   // descending overall
                    if (sw) { s_keys[i] = b; s_keys[ixj] = a; }
                }
            }
            __syncthreads();
        }
    }
    for (int i = threadIdx.x; i < cap; i += blockDim.x) {
        unsigned idx = 0xFFFFFFFFu - (unsigned)(s_keys[i] & 0xFFFFFFFFull);
        ids[e * cap + i]    = (int)idx;
        tscore[e * cap + i] = s[idx];
    }
}

// ---------------- generic NT GEMM: C[m,n] = sum_k A[m,k]*B[n,k] -------------
// 128x128 tile, BK=16, 256 threads, 8x8 microtile, double-buffered smem.
// EPI: 0 = silu(acc+bias) store        (expert gate / shared gate)
//      1 = (acc+bias) * C_old store    (expert up / shared up, GLU multiply)
//      2 = atomicAdd(out[tok], (acc+bias)*rowScale)   (expert down + combine)
//      3 = plain store                  (shared down)
struct GemmArgs {
    const float* A; long long aStride; int lda;
    const float* B; long long bStride;                 // ldb == K
    float* C;       long long cStride; int ldc;
    const float* bias; long long biasStride;
    const int*   gatherA;                              // per-batch stride = M
    const float* rowScale;                             // per-batch stride = M
    const int*   scatterRows;                          // per-batch stride = M
    float* scatterOut; int scatterLd;
    int M, N, K;
};

template <int EPI>
__global__ __launch_bounds__(256, 2)
void gemm_nt(GemmArgs p) {
    __shared__ float As[2][16][132];
    __shared__ float Bs[2][16][132];
    __shared__ int   rowIds[128];

    const int b = blockIdx.z;
    const float* A    = p.A + (long long)b * p.aStride;
    const float* B    = p.B + (long long)b * p.bStride;
    float* C          = p.C ? p.C + (long long)b * p.cStride : nullptr;
    const float* bias = p.bias ? p.bias + (long long)b * p.biasStride : nullptr;
    const int*   gA   = p.gatherA ? p.gatherA + (long long)b * p.M : nullptr;
    const float* rsc  = p.rowScale ? p.rowScale + (long long)b * p.M : nullptr;
    const int*   srow = p.scatterRows ? p.scatterRows + (long long)b * p.M : nullptr;

    const int m0 = blockIdx.y * 128;
    const int n0 = blockIdx.x * 128;
    const int tid = threadIdx.x;

    if (tid < 128) rowIds[tid] = gA ? gA[m0 + tid] : (m0 + tid);
    __syncthreads();

    const int lr = tid >> 2;            // 0..63
    const int lc = (tid & 3) << 2;      // 0,4,8,12
    const int K  = p.K;
    const int ntiles = K >> 4;

    const float* Ar0 = A + (long long)rowIds[lr]      * p.lda + lc;
    const float* Ar1 = A + (long long)rowIds[lr + 64] * p.lda + lc;
    const float* Br0 = B + (long long)(n0 + lr)       * K     + lc;
    const float* Br1 = B + (long long)(n0 + lr + 64)  * K     + lc;

    float4 ra0 = *(const float4*)(Ar0);
    float4 ra1 = *(const float4*)(Ar1);
    float4 rb0 = *(const float4*)(Br0);
    float4 rb1 = *(const float4*)(Br1);

    float acc[8][8];
#pragma unroll
    for (int i = 0; i < 8; i++)
#pragma unroll
        for (int j = 0; j < 8; j++) acc[i][j] = 0.f;

    // stage tile 0
    As[0][lc + 0][lr] = ra0.x; As[0][lc + 1][lr] = ra0.y;
    As[0][lc + 2][lr] = ra0.z; As[0][lc + 3][lr] = ra0.w;
    As[0][lc + 0][lr + 64] = ra1.x; As[0][lc + 1][lr + 64] = ra1.y;
    As[0][lc + 2][lr + 64] = ra1.z; As[0][lc + 3][lr + 64] = ra1.w;
    Bs[0][lc + 0][lr] = rb0.x; Bs[0][lc + 1][lr] = rb0.y;
    Bs[0][lc + 2][lr] = rb0.z; Bs[0][lc + 3][lr] = rb0.w;
    Bs[0][lc + 0][lr + 64] = rb1.x; Bs[0][lc + 1][lr + 64] = rb1.y;
    Bs[0][lc + 2][lr + 64] = rb1.z; Bs[0][lc + 3][lr + 64] = rb1.w;
    __syncthreads();

    const int ty4 = (tid >> 4) << 2;
    const int tx4 = (tid & 15) << 2;

    for (int kt = 0; kt < ntiles; kt++) {
        const int buf = kt & 1;
        if (kt + 1 < ntiles) {
            const int ko = (kt + 1) << 4;
            ra0 = *(const float4*)(Ar0 + ko);
            ra1 = *(const float4*)(Ar1 + ko);
            rb0 = *(const float4*)(Br0 + ko);
            rb1 = *(const float4*)(Br1 + ko);
        }
#pragma unroll
        for (int kk = 0; kk < 16; kk++) {
            float4 a0 = *(const float4*)&As[buf][kk][ty4];
            float4 a1 = *(const float4*)&As[buf][kk][64 + ty4];
            float4 b0 = *(const float4*)&Bs[buf][kk][tx4];
            float4 b1 = *(const float4*)&Bs[buf][kk][64 + tx4];
            float av[8] = {a0.x, a0.y, a0.z, a0.w, a1.x, a1.y, a1.z, a1.w};
            float bv[8] = {b0.x, b0.y, b0.z, b0.w, b1.x, b1.y, b1.z, b1.w};
#pragma unroll
            for (int i = 0; i < 8; i++)
#pragma unroll
                for (int j = 0; j < 8; j++)
                    acc[i][j] = fmaf(av[i], bv[j], acc[i][j]);
        }
        if (kt + 1 < ntiles) {
            const int nb = (kt + 1) & 1;
            As[nb][lc + 0][lr] = ra0.x; As[nb][lc + 1][lr] = ra0.y;
            As[nb][lc + 2][lr] = ra0.z; As[nb][lc + 3][lr] = ra0.w;
            As[nb][lc + 0][lr + 64] = ra1.x; As[nb][lc + 1][lr + 64] = ra1.y;
            As[nb][lc + 2][lr + 64] = ra1.z; As[nb][lc + 3][lr + 64] = ra1.w;
            Bs[nb][lc + 0][lr] = rb0.x; Bs[nb][lc + 1][lr] = rb0.y;
            Bs[nb][lc + 2][lr] = rb0.z; Bs[nb][lc + 3][lr] = rb0.w;
            Bs[nb][lc + 0][lr + 64] = rb1.x; Bs[nb][lc + 1][lr + 64] = rb1.y;
            Bs[nb][lc + 2][lr + 64] = rb1.z; Bs[nb][lc + 3][lr + 64] = rb1.w;
        }
        __syncthreads();
    }

    // epilogue
    float bn[8];
#pragma unroll
    for (int j = 0; j < 8; j++) {
        int n = n0 + ((j < 4) ? (tx4 + j) : (64 + tx4 + j - 4));
        bn[j] = bias ? bias[n] : 0.f;
    }

#pragma unroll
    for (int i = 0; i < 8; i++) {
        int m = m0 + ((i < 4) ? (ty4 + i) : (64 + ty4 + i - 4));
        if (EPI == 2) {
            int   tok = srow[m];
            float sc  = rsc[m];
            float* orow = p.scatterOut + (long long)tok * p.scatterLd + n0;
#pragma unroll
            for (int j = 0; j < 8; j++) {
                int nn = (j < 4) ? (tx4 + j) : (64 + tx4 + j - 4);
                atomicAdd(orow + nn, (acc[i][j] + bn[j]) * sc);
            }
        } else {
            float* crow = C + (long long)m * p.ldc + n0;
            float t0[4], t1[4];
#pragma unroll
            for (int j = 0; j < 4; j++) {
                t0[j] = acc[i][j]     + bn[j];
                t1[j] = acc[i][j + 4] + bn[j + 4];
            }
            if (EPI == 0) {
#pragma unroll
                for (int j = 0; j < 4; j++) { t0[j] = siluf_(t0[j]); t1[j] = siluf_(t1[j]); }
            } else if (EPI == 1) {
                float4 o0 = *(const float4*)(crow + tx4);
                float4 o1 = *(const float4*)(crow + 64 + tx4);
                t0[0] *= o0.x; t0[1] *= o0.y; t0[2] *= o0.z; t0[3] *= o0.w;
                t1[0] *= o1.x; t1[1] *= o1.y; t1[2] *= o1.z; t1[3] *= o1.w;
            }
            *(float4*)(crow + tx4)      = make_float4(t0[0], t0[1], t0[2], t0[3]);
            *(float4*)(crow + 64 + tx4) = make_float4(t1[0], t1[1], t1[2], t1[3]);
        }
    }
}

// ---------------- launch ----------------------------------------------------
extern "C" void kernel_launch(void* const* d_in, const int* in_sizes, int n_in,
                              void* d_out, int out_size) {
    const float* x      = (const float*)d_in[0];
    const float* gate_w = (const float*)d_in[1];
    const float* up_w   = (const float*)d_in[2];
    const float* up_b   = (const float*)d_in[3];
    const float* gw     = (const float*)d_in[4];
    const float* gb     = (const float*)d_in[5];
    const float* down_w = (const float*)d_in[6];
    const float* down_b = (const float*)d_in[7];
    const float* shg    = (const float*)d_in[8];
    const float* shu    = (const float*)d_in[9];
    (void)n_in; (void)out_size;
    const float* shd    = (const float*)d_in[10];
    float* out = (float*)d_out;

    int T   = in_sizes[0] / DIM;                 // 8192
    int cap = (T * 2 + NEXP - 1) / NEXP;         // 1024

    float *scoresT, *tscore, *act, *shact; int* ids;
    cudaGetSymbolAddress((void**)&scoresT, g_scoresT);
    cudaGetSymbolAddress((void**)&ids,     g_ids);
    cudaGetSymbolAddress((void**)&tscore,  g_tscore);
    cudaGetSymbolAddress((void**)&act,     g_act);
    cudaGetSymbolAddress((void**)&shact,   g_shact);

    // 1) gate scores (transposed layout for top-k)
    gate_kernel<<<(T + 7) / 8, 256>>>(x, gate_w, scoresT, T);

    // 2) exact per-expert top-cap selection
    cudaFuncSetAttribute(topk_kernel, cudaFuncAttributeMaxDynamicSharedMemorySize,
                         NSORT * (int)sizeof(unsigned long long));
    topk_kernel<<<NEXP, 1024, NSORT * (int)sizeof(unsigned long long)>>>(
        scoresT, ids, tscore, T, cap);

    // 3) shared GLU MLP (writes `out` with plain stores — initializes it)
    GemmArgs s1{};
    s1.A = x;     s1.aStride = 0; s1.lda = DIM;
    s1.B = shg;   s1.bStride = 0;
    s1.C = shact; s1.cStride = 0; s1.ldc = SHDIM;
    s1.M = T; s1.N = SHDIM; s1.K = DIM;
    gemm_nt<0><<<dim3(SHDIM / 128, T / 128, 1), 256>>>(s1);

    GemmArgs s2 = s1; s2.B = shu;
    gemm_nt<1><<<dim3(SHDIM / 128, T / 128, 1), 256>>>(s2);

    GemmArgs s3{};
    s3.A = shact; s3.aStride = 0; s3.lda = SHDIM;
    s3.B = shd;   s3.bStride = 0;
    s3.C = out;   s3.cStride = 0; s3.ldc = DIM;
    s3.M = T; s3.N = DIM; s3.K = SHDIM;
    gemm_nt<3><<<dim3(DIM / 128, T / 128, 1), 256>>>(s3);

    // 4) expert GLU: gate -> silu (EPI0), up * silu(gate) (EPI1)
    GemmArgs e1{};
    e1.A = x;   e1.aStride = 0; e1.lda = DIM;
    e1.B = gw;  e1.bStride = (long long)FDIM * DIM;
    e1.C = act; e1.cStride = (long long)cap * FDIM; e1.ldc = FDIM;
    e1.bias = gb; e1.biasStride = FDIM;
    e1.gatherA = ids;
    e1.M = cap; e1.N = FDIM; e1.K = DIM;
    gemm_nt<0><<<dim3(FDIM / 128, cap / 128, NEXP), 256>>>(e1);

    GemmArgs e2 = e1; e2.B = up_w; e2.bias = up_b;
    gemm_nt<1><<<dim3(FDIM / 128, cap / 128, NEXP), 256>>>(e2);

    // 5) expert down + weighted scatter-add combine (after shared wrote `out`)
    GemmArgs e3{};
    e3.A = act;    e3.aStride = (long long)cap * FDIM; e3.lda = FDIM;
    e3.B = down_w; e3.bStride = (long long)DIM * FDIM;
    e3.C = nullptr; e3.cStride = 0; e3.ldc = 0;
    e3.bias = down_b; e3.biasStride = DIM;
    e3.scatterRows = ids; e3.rowScale = tscore;
    e3.scatterOut = out;  e3.scatterLd = DIM;
    e3.M = cap; e3.N = DIM; e3.K = FDIM;
    gemm_nt<2><<<dim3(DIM / 128, cap / 128, NEXP), 256>>>(e3);
}

// round 5
// speedup vs baseline: 1.6338x; 1.6338x over previous
#include <cuda_runtime.h>
#include <cuda_bf16.h>
#include <math.h>
#include <stdint.h>

typedef unsigned int u32;
typedef unsigned long long u64;

#define NEXP 16
#define DIM 1024
#define FDIM 4096
#define SHDIM 2048
#define MAXT 8192
#define NSORT 8192
#define MAXCAP 1024

// ---------------- static scratch ----------------
constexpr size_t SZ_X  = (size_t)MAXT * DIM * 2;
constexpr size_t SZ_W  = (size_t)NEXP * FDIM * DIM * 2;
constexpr size_t SZ_SW = (size_t)SHDIM * DIM * 2;
constexpr size_t SZ_EA = (size_t)NEXP * MAXCAP * FDIM * 2;
constexpr size_t SZ_SA = (size_t)MAXT * SHDIM * 2;
constexpr size_t O_XH = 0,              O_XL = O_XH + SZ_X;
constexpr size_t O_WGH = O_XL + SZ_X,   O_WGL = O_WGH + SZ_W;
constexpr size_t O_WUH = O_WGL + SZ_W,  O_WUL = O_WUH + SZ_W;
constexpr size_t O_WDH = O_WUL + SZ_W,  O_WDL = O_WDH + SZ_W;
constexpr size_t O_SGH = O_WDL + SZ_W,  O_SGL = O_SGH + SZ_SW;
constexpr size_t O_SUH = O_SGL + SZ_SW, O_SUL = O_SUH + SZ_SW;
constexpr size_t O_SDH = O_SUL + SZ_SW, O_SDL = O_SDH + SZ_SW;
constexpr size_t O_EGH = O_SDL + SZ_SW, O_EGL = O_EGH + SZ_EA;   // expert silu(gate)
constexpr size_t O_EAH = O_EGL + SZ_EA, O_EAL = O_EAH + SZ_EA;   // expert act
constexpr size_t O_SSH = O_EAL + SZ_EA, O_SSL = O_SSH + SZ_SA;   // shared silu(gate)
constexpr size_t O_SAH = O_SSL + SZ_SA, O_SAL = O_SAH + SZ_SA;   // shared act
constexpr size_t O_SC  = O_SAL + SZ_SA;
constexpr size_t O_IDS = O_SC + (size_t)NEXP * MAXT * 4;
constexpr size_t O_TSC = O_IDS + (size_t)NEXP * MAXCAP * 4;
constexpr size_t TOTAL = O_TSC + (size_t)NEXP * MAXCAP * 4;
__device__ __align__(1024) unsigned char g_buf[TOTAL];

// ---------------- helpers ----------------
__device__ __forceinline__ u32 smem_u32(const void* p) {
    u32 a;
    asm("{ .reg .u64 t; cvta.to.shared.u64 t, %1; cvt.u32.u64 %0, t; }" : "=r"(a) : "l"(p));
    return a;
}
__device__ __forceinline__ void cpa16(u32 dst, const void* src) {
    asm volatile("cp.async.cg.shared.global [%0], [%1], 16;" :: "r"(dst), "l"(src) : "memory");
}
#define CP_COMMIT() asm volatile("cp.async.commit_group;" ::: "memory")
#define CP_WAIT1()  asm volatile("cp.async.wait_group 1;" ::: "memory")
#define CP_WAIT0()  asm volatile("cp.async.wait_group 0;" ::: "memory")
#define LDM4(R, a) \
    asm volatile("ldmatrix.sync.aligned.m8n8.x4.shared.b16 {%0,%1,%2,%3}, [%4];" \
        : "=r"((R)[0]), "=r"((R)[1]), "=r"((R)[2]), "=r"((R)[3]) : "r"(a))
#define MMA(c, A, b0, b1) \
    asm volatile("mma.sync.aligned.m16n8k16.row.col.f32.bf16.bf16.f32 " \
        "{%0,%1,%2,%3}, {%4,%5,%6,%7}, {%8,%9}, {%0,%1,%2,%3};" \
        : "+f"((c)[0]), "+f"((c)[1]), "+f"((c)[2]), "+f"((c)[3]) \
        : "r"((A)[0]), "r"((A)[1]), "r"((A)[2]), "r"((A)[3]), "r"(b0), "r"(b1))

__device__ __forceinline__ u32 packbf2(float a, float b) {
    u32 r;
    asm("cvt.rn.bf16x2.f32 %0, %1, %2;" : "=r"(r) : "f"(b), "f"(a));  // lo=a hi=b
    return r;
}
__device__ __forceinline__ void split2(float a, float b, u32& h, u32& l) {
    h = packbf2(a, b);
    l = packbf2(a - __uint_as_float(h << 16), b - __uint_as_float(h & 0xFFFF0000u));
}
__device__ __forceinline__ float sigmoidf_(float x) { return 1.f / (1.f + expf(-x)); }
__device__ __forceinline__ float siluf_(float x)    { return __fdividef(x, 1.f + __expf(-x)); }

// ---------------- fp32 -> bf16 hi/lo split ----------------
__global__ void splitk(const float4* __restrict__ in, uint2* __restrict__ oh,
                       uint2* __restrict__ ol, long n4) {
    long i = blockIdx.x * (long)blockDim.x + threadIdx.x;
    long st = (long)gridDim.x * blockDim.x;
    for (; i < n4; i += st) {
        float4 q = in[i];
        u32 h0, l0, h1, l1;
        split2(q.x, q.y, h0, l0);
        split2(q.z, q.w, h1, l1);
        oh[i] = make_uint2(h0, h1);
        ol[i] = make_uint2(l0, l1);
    }
}

// ---------------- gate scores (exact fp32 for stable ranking) ----------------
__global__ void gate_kernel(const float* __restrict__ h, const float* __restrict__ gate_w,
                            float* __restrict__ scoresT, int T) {
    int warp = (int)((blockIdx.x * blockDim.x + threadIdx.x) >> 5);
    int lane = threadIdx.x & 31;
    if (warp >= T) return;
    const float* hr = h + (size_t)warp * DIM;
    float hreg[32];
#pragma unroll
    for (int i = 0; i < 32; i++) hreg[i] = hr[lane + 32 * i];
#pragma unroll
    for (int e = 0; e < NEXP; e++) {
        const float* w = gate_w + e * DIM;
        float s = 0.f;
#pragma unroll
        for (int i = 0; i < 32; i++) s = fmaf(hreg[i], w[lane + 32 * i], s);
#pragma unroll
        for (int o = 16; o; o >>= 1) s += __shfl_xor_sync(0xffffffffu, s, o);
        if (lane == 0) scoresT[e * T + warp] = sigmoidf_(s);
    }
}

// ---------------- exact top-k (matches jax.lax.top_k ties) ----------------
__global__ void topk_kernel(const float* __restrict__ scoresT, int* __restrict__ ids,
                            float* __restrict__ tscore, int T, int cap) {
    extern __shared__ u64 s_keys[];
    int e = blockIdx.x;
    const float* s = scoresT + (size_t)e * T;
    for (int i = threadIdx.x; i < NSORT; i += blockDim.x) {
        float v = (i < T) ? s[i] : -1e30f;
        u32 u = __float_as_uint(v);
        u32 ob = (u & 0x80000000u) ? ~u : (u | 0x80000000u);
        s_keys[i] = ((u64)ob << 32) | (u32)(0xFFFFFFFFu - (u32)i);
    }
    __syncthreads();
    for (u32 k = 2; k <= NSORT; k <<= 1)
        for (u32 j = k >> 1; j > 0; j >>= 1) {
            for (u32 i = threadIdx.x; i < NSORT; i += blockDim.x) {
                u32 ixj = i ^ j;
                if (ixj > i) {
                    u64 a = s_keys[i], b = s_keys[ixj];
                    if (((i & k) == 0) ? (a < b) : (a > b)) { s_keys[i] = b; s_keys[ixj] = a; }
                }
            }
            __syncthreads();
        }
    for (int i = threadIdx.x; i < cap; i += blockDim.x) {
        u32 idx = 0xFFFFFFFFu - (u32)(s_keys[i] & 0xFFFFFFFFull);
        ids[e * cap + i] = (int)idx;
        tscore[e * cap + i] = s[idx];
    }
}

// ========== tensor-core GEMM: C = A@B^T, split-bf16 3-term ==========
// EPI 0: silu(acc+bias) -> bf16 hi/lo      1: (acc+bias)*aux -> bf16 hi/lo
//     2: atomicAdd(out[tok], (acc+bias)*score)      3: plain f32 store
struct GArgs {
    const char* Ah; const char* Al; long long aStrE; int K;
    const int* gids; int cap;
    const char* Bh; const char* Bl; long long bStrE;
    const float* bias; long long biasStrE;
    const char* auxH; const char* auxL; long long auxStrE;
    char* oH; char* oL; long long oStrE; int ldo;
    float* oF;
    const float* tsc;
};

#define MM_SMEM 196608   // 3 stages x 4 tiles x 16KB

template <int EPI>
__global__ __launch_bounds__(256, 1) void mm(GArgs g) {
    extern __shared__ char smem[];
    const u32 sb = smem_u32(smem);
    __shared__ int rows[128];
    const int tid = threadIdx.x, lane = tid & 31, wid = tid >> 5;
    const int e = blockIdx.z, n0 = blockIdx.x * 128, m0 = blockIdx.y * 128;

    if (tid < 128) rows[tid] = (g.gids && EPI != 2) ? g.gids[e * g.cap + m0 + tid] : (m0 + tid);
    __syncthreads();

    const int r = tid >> 1, hf = tid & 1;
    const char* pAh = g.Ah + ((size_t)e * g.aStrE + (size_t)rows[r] * g.K + hf * 32) * 2;
    const char* pAl = g.Al + ((size_t)e * g.aStrE + (size_t)rows[r] * g.K + hf * 32) * 2;
    const char* pBh = g.Bh + ((size_t)e * g.bStrE + (size_t)(n0 + r) * g.K + hf * 32) * 2;
    const char* pBl = g.Bl + ((size_t)e * g.bStrE + (size_t)(n0 + r) * g.K + hf * 32) * 2;
    u32 dst[4];
#pragma unroll
    for (int i = 0; i < 4; i++) {
        u32 o = r * 128 + hf * 64 + i * 16;
        dst[i] = o ^ ((o >> 3) & 0x70);
    }

    const int wm = (wid >> 2) * 64, wn = (wid & 3) * 32;
    const u32 xv = (lane & 7) << 4;
    const u32 hib = (lane >> 4) * 16;
    u32 aoffs[4], boffs[2];
#pragma unroll
    for (int mi = 0; mi < 4; mi++) aoffs[mi] = (wm + mi * 16 + (lane & 15)) * 128;
#pragma unroll
    for (int nh = 0; nh < 2; nh++) boffs[nh] = (wn + nh * 16 + (lane & 15)) * 128;

    float acc[4][4][4];
#pragma unroll
    for (int a = 0; a < 4; a++)
#pragma unroll
        for (int b = 0; b < 4; b++)
#pragma unroll
            for (int c = 0; c < 4; c++) acc[a][b][c] = 0.f;

    auto load_stage = [&](int s, int kt) {
        u32 st = sb + s * 65536;
        size_t kb = (size_t)kt * 128;
#pragma unroll
        for (int i = 0; i < 4; i++) {
            cpa16(st + dst[i],         pAh + kb + i * 16);
            cpa16(st + 16384 + dst[i], pAl + kb + i * 16);
            cpa16(st + 32768 + dst[i], pBh + kb + i * 16);
            cpa16(st + 49152 + dst[i], pBl + kb + i * 16);
        }
    };

    const int NT = g.K >> 6;
    load_stage(0, 0); CP_COMMIT();
    load_stage(1, 1); CP_COMMIT();

    for (int kt = 0; kt < NT; kt++) {
        if (kt < NT - 1) CP_WAIT1(); else CP_WAIT0();
        __syncthreads();
        if (kt + 2 < NT) { load_stage((kt + 2) % 3, kt + 2); CP_COMMIT(); }
        const u32 stb = sb + (kt % 3) * 65536;
#pragma unroll
        for (int ks = 0; ks < 4; ks++) {
            const u32 kx = ks * 32 + hib;
            u32 ah[4][4], al[4][4], bhf[2][4], blf[2][4];
#pragma unroll
            for (int mi = 0; mi < 4; mi++) {
                u32 ad = stb + aoffs[mi] + (kx ^ xv);
                LDM4(ah[mi], ad);
                LDM4(al[mi], ad + 16384);
            }
#pragma unroll
            for (int nh = 0; nh < 2; nh++) {
                u32 bd = stb + 32768 + boffs[nh] + (kx ^ xv);
                LDM4(bhf[nh], bd);
                LDM4(blf[nh], bd + 16384);
            }
#pragma unroll
            for (int mi = 0; mi < 4; mi++)
#pragma unroll
                for (int ni = 0; ni < 4; ni++) {
                    const int nh = ni >> 1, o = ni & 1;
                    MMA(acc[mi][ni], ah[mi], bhf[nh][o], bhf[nh][2 + o]);
                    MMA(acc[mi][ni], ah[mi], blf[nh][o], blf[nh][2 + o]);
                    MMA(acc[mi][ni], al[mi], bhf[nh][o], bhf[nh][2 + o]);
                }
        }
        __syncthreads();
    }

    // ---------------- epilogue ----------------
    const float* bias = g.bias ? g.bias + (size_t)e * g.biasStrE : nullptr;
#pragma unroll
    for (int mi = 0; mi < 4; mi++)
#pragma unroll
        for (int ni = 0; ni < 4; ni++) {
            const int lr = wm + mi * 16 + (lane >> 2);
            const int col = wn + ni * 8 + (lane & 3) * 2;
            const int n = n0 + col;
            float b0 = 0.f, b1 = 0.f;
            if (bias) { b0 = bias[n]; b1 = bias[n + 1]; }
            float v[4] = {acc[mi][ni][0] + b0, acc[mi][ni][1] + b1,
                          acc[mi][ni][2] + b0, acc[mi][ni][3] + b1};
            if (EPI == 2) {
#pragma unroll
                for (int hrow = 0; hrow < 2; hrow++) {
                    int sl = e * g.cap + m0 + lr + hrow * 8;
                    int tok = g.gids[sl];
                    float sc = g.tsc[sl];
                    float* orow = g.oF + (size_t)tok * DIM + n;
                    atomicAdd(orow,     v[2 * hrow]     * sc);
                    atomicAdd(orow + 1, v[2 * hrow + 1] * sc);
                }
            } else if (EPI == 3) {
                size_t off = (size_t)(m0 + lr) * g.ldo + n;
                g.oF[off] = v[0]; g.oF[off + 1] = v[1];
                g.oF[off + 8 * g.ldo] = v[2]; g.oF[off + 8 * g.ldo + 1] = v[3];
            } else {
#pragma unroll
                for (int hrow = 0; hrow < 2; hrow++) {
                    size_t off = (size_t)e * g.oStrE + (size_t)(m0 + lr + hrow * 8) * g.ldo + n;
                    float v0 = v[2 * hrow], v1 = v[2 * hrow + 1];
                    if (EPI == 0) { v0 = siluf_(v0); v1 = siluf_(v1); }
                    else {
                        u32 ph = *(const u32*)(g.auxH + ((size_t)e * g.auxStrE +
                                  (size_t)(m0 + lr + hrow * 8) * g.ldo + n) * 2);
                        u32 pl = *(const u32*)(g.auxL + ((size_t)e * g.auxStrE +
                                  (size_t)(m0 + lr + hrow * 8) * g.ldo + n) * 2);
                        float a0 = __uint_as_float(ph << 16) + __uint_as_float(pl << 16);
                        float a1 = __uint_as_float(ph & 0xFFFF0000u) + __uint_as_float(pl & 0xFFFF0000u);
                        v0 *= a0; v1 *= a1;
                    }
                    u32 h, l;
                    split2(v0, v1, h, l);
                    *(u32*)(g.oH + off * 2) = h;
                    *(u32*)(g.oL + off * 2) = l;
                }
            }
        }
}

// ---------------- launch ----------------
extern "C" void kernel_launch(void* const* d_in, const int* in_sizes, int n_in,
                              void* d_out, int out_size) {
    const float* x      = (const float*)d_in[0];
    const float* gate_w = (const float*)d_in[1];
    const float* up_w   = (const float*)d_in[2];
    const float* up_b   = (const float*)d_in[3];
    const float* gw     = (const float*)d_in[4];
    const float* gb     = (const float*)d_in[5];
    const float* down_w = (const float*)d_in[6];
    const float* down_b = (const float*)d_in[7];
    const float* shg    = (const float*)d_in[8];
    const float* shu    = (const float*)d_in[9];
    const float* shd    = (const float*)d_in[10];
    (void)n_in; (void)out_size;
    float* out = (float*)d_out;

    int T = in_sizes[0] / DIM;               // 8192
    int cap = (T * 2 + NEXP - 1) / NEXP;     // 1024

    unsigned char* buf;
    cudaGetSymbolAddress((void**)&buf, g_buf);
    float* scoresT = (float*)(buf + O_SC);
    int*   ids     = (int*)(buf + O_IDS);
    float* tsc     = (float*)(buf + O_TSC);

    static bool s_init = false;
    if (!s_init) {
        s_init = true;
        cudaFuncSetAttribute(topk_kernel, cudaFuncAttributeMaxDynamicSharedMemorySize,
                             NSORT * (int)sizeof(u64));
        cudaFuncSetAttribute(mm<0>, cudaFuncAttributeMaxDynamicSharedMemorySize, MM_SMEM);
        cudaFuncSetAttribute(mm<1>, cudaFuncAttributeMaxDynamicSharedMemorySize, MM_SMEM);
        cudaFuncSetAttribute(mm<2>, cudaFuncAttributeMaxDynamicSharedMemorySize, MM_SMEM);
        cudaFuncSetAttribute(mm<3>, cudaFuncAttributeMaxDynamicSharedMemorySize, MM_SMEM);
    }

    // 1) splits
    splitk<<<1024, 256>>>((const float4*)x, (uint2*)(buf + O_XH), (uint2*)(buf + O_XL),
                          (long)((size_t)T * DIM / 4));
    long w4 = (long)((size_t)NEXP * FDIM * DIM / 4);
    splitk<<<4096, 256>>>((const float4*)gw,     (uint2*)(buf + O_WGH), (uint2*)(buf + O_WGL), w4);
    splitk<<<4096, 256>>>((const float4*)up_w,   (uint2*)(buf + O_WUH), (uint2*)(buf + O_WUL), w4);
    splitk<<<4096, 256>>>((const float4*)down_w, (uint2*)(buf + O_WDH), (uint2*)(buf + O_WDL), w4);
    long s4 = (long)((size_t)SHDIM * DIM / 4);
    splitk<<<512, 256>>>((const float4*)shg, (uint2*)(buf + O_SGH), (uint2*)(buf + O_SGL), s4);
    splitk<<<512, 256>>>((const float4*)shu, (uint2*)(buf + O_SUH), (uint2*)(buf + O_SUL), s4);
    splitk<<<512, 256>>>((const float4*)shd, (uint2*)(buf + O_SDH), (uint2*)(buf + O_SDL), s4);

    // 2) gate + top-k
    gate_kernel<<<(T + 7) / 8, 256>>>(x, gate_w, scoresT, T);
    topk_kernel<<<NEXP, 1024, NSORT * (int)sizeof(u64)>>>(scoresT, ids, tsc, T, cap);

    GArgs a{};
    // 3) shared gate: silu(x@shg^T) -> SSH/SSL
    a = GArgs{};
    a.Ah = (char*)(buf + O_XH); a.Al = (char*)(buf + O_XL); a.aStrE = 0; a.K = DIM;
    a.Bh = (char*)(buf + O_SGH); a.Bl = (char*)(buf + O_SGL); a.bStrE = 0;
    a.oH = (char*)(buf + O_SSH); a.oL = (char*)(buf + O_SSL); a.oStrE = 0; a.ldo = SHDIM;
    mm<0><<<dim3(SHDIM / 128, T / 128, 1), 256, MM_SMEM>>>(a);

    // 4) shared up: (x@shu^T) * silu -> SAH/SAL
    a.Bh = (char*)(buf + O_SUH); a.Bl = (char*)(buf + O_SUL);
    a.auxH = (char*)(buf + O_SSH); a.auxL = (char*)(buf + O_SSL); a.auxStrE = 0;
    a.oH = (char*)(buf + O_SAH); a.oL = (char*)(buf + O_SAL);
    mm<1><<<dim3(SHDIM / 128, T / 128, 1), 256, MM_SMEM>>>(a);

    // 5) shared down -> out (plain f32 store initializes out)
    a = GArgs{};
    a.Ah = (char*)(buf + O_SAH); a.Al = (char*)(buf + O_SAL); a.aStrE = 0; a.K = SHDIM;
    a.Bh = (char*)(buf + O_SDH); a.Bl = (char*)(buf + O_SDL); a.bStrE = 0;
    a.oF = out; a.ldo = DIM;
    mm<3><<<dim3(DIM / 128, T / 128, 1), 256, MM_SMEM>>>(a);

    // 6) expert gate: silu(x[ids]@gw^T + gb) -> EGH/EGL
    a = GArgs{};
    a.Ah = (char*)(buf + O_XH); a.Al = (char*)(buf + O_XL); a.aStrE = 0; a.K = DIM;
    a.gids = ids; a.cap = cap;
    a.Bh = (char*)(buf + O_WGH); a.Bl = (char*)(buf + O_WGL); a.bStrE = (long long)FDIM * DIM;
    a.bias = gb; a.biasStrE = FDIM;
    a.oH = (char*)(buf + O_EGH); a.oL = (char*)(buf + O_EGL);
    a.oStrE = (long long)cap * FDIM; a.ldo = FDIM;
    mm<0><<<dim3(FDIM / 128, cap / 128, NEXP), 256, MM_SMEM>>>(a);

    // 7) expert up: (x[ids]@up_w^T + up_b) * silu -> EAH/EAL
    a.Bh = (char*)(buf + O_WUH); a.Bl = (char*)(buf + O_WUL);
    a.bias = up_b;
    a.auxH = (char*)(buf + O_EGH); a.auxL = (char*)(buf + O_EGL);
    a.auxStrE = (long long)cap * FDIM;
    a.oH = (char*)(buf + O_EAH); a.oL = (char*)(buf + O_EAL);
    mm<1><<<dim3(FDIM / 128, cap / 128, NEXP), 256, MM_SMEM>>>(a);

    // 8) expert down + weighted scatter-add
    a = GArgs{};
    a.Ah = (char*)(buf + O_EAH); a.Al = (char*)(buf + O_EAL);
    a.aStrE = (long long)cap * FDIM; a.K = FDIM;
    a.gids = ids; a.cap = cap; a.tsc = tsc;
    a.Bh = (char*)(buf + O_WDH); a.Bl = (char*)(buf + O_WDL); a.bStrE = (long long)DIM * FDIM;
    a.bias = down_b; a.biasStrE = DIM;
    a.oF = out; a.ldo = DIM;
    mm<2><<<dim3(DIM / 128, cap / 128, NEXP), 256, MM_SMEM>>>(a);
}

// round 7
// speedup vs baseline: 1.7681x; 1.0822x over previous
#include <cuda_runtime.h>
#include <cuda_bf16.h>
#include <math.h>
#include <stdint.h>

typedef unsigned int u32;
typedef unsigned long long u64;

#define NEXP 16
#define DIM 1024
#define FDIM 4096
#define SHDIM 2048
#define MAXT 8192
#define NSORT 8192
#define MAXCAP 1024

// ---------------- static scratch ----------------
constexpr size_t SZ_X  = (size_t)MAXT * DIM * 2;
constexpr size_t SZ_W  = (size_t)NEXP * FDIM * DIM * 2;
constexpr size_t SZ_SW = (size_t)SHDIM * DIM * 2;
constexpr size_t SZ_EA = (size_t)NEXP * MAXCAP * FDIM * 2;
constexpr size_t SZ_SA = (size_t)MAXT * SHDIM * 2;
constexpr size_t O_XH = 0,              O_XL = O_XH + SZ_X;
constexpr size_t O_WGH = O_XL + SZ_X,   O_WGL = O_WGH + SZ_W;
constexpr size_t O_WUH = O_WGL + SZ_W,  O_WUL = O_WUH + SZ_W;
constexpr size_t O_WDH = O_WUL + SZ_W,  O_WDL = O_WDH + SZ_W;
constexpr size_t O_SGH = O_WDL + SZ_W,  O_SGL = O_SGH + SZ_SW;
constexpr size_t O_SUH = O_SGL + SZ_SW, O_SUL = O_SUH + SZ_SW;
constexpr size_t O_SDH = O_SUL + SZ_SW, O_SDL = O_SDH + SZ_SW;
constexpr size_t O_EGH = O_SDL + SZ_SW, O_EGL = O_EGH + SZ_EA;   // expert silu(gate)
constexpr size_t O_EAH = O_EGL + SZ_EA, O_EAL = O_EAH + SZ_EA;   // expert act
constexpr size_t O_SSH = O_EAL + SZ_EA, O_SSL = O_SSH + SZ_SA;   // shared silu(gate)
constexpr size_t O_SAH = O_SSL + SZ_SA, O_SAL = O_SAH + SZ_SA;   // shared act
constexpr size_t O_SC  = O_SAL + SZ_SA;
constexpr size_t O_IDS = O_SC + (size_t)NEXP * MAXT * 4;
constexpr size_t O_TSC = O_IDS + (size_t)NEXP * MAXCAP * 4;
constexpr size_t TOTAL = O_TSC + (size_t)NEXP * MAXCAP * 4;
__device__ __align__(1024) unsigned char g_buf[TOTAL];

// ---------------- helpers ----------------
__device__ __forceinline__ u32 smem_u32(const void* p) {
    u32 a;
    asm("{ .reg .u64 t; cvta.to.shared.u64 t, %1; cvt.u32.u64 %0, t; }" : "=r"(a) : "l"(p));
    return a;
}
__device__ __forceinline__ void cpa16(u32 dst, const void* src) {
    asm volatile("cp.async.cg.shared.global [%0], [%1], 16;" :: "r"(dst), "l"(src) : "memory");
}
#define CP_COMMIT() asm volatile("cp.async.commit_group;" ::: "memory")
#define CP_WAIT1()  asm volatile("cp.async.wait_group 1;" ::: "memory")
#define CP_WAIT0()  asm volatile("cp.async.wait_group 0;" ::: "memory")
#define LDM4(R, a) \
    asm volatile("ldmatrix.sync.aligned.m8n8.x4.shared.b16 {%0,%1,%2,%3}, [%4];" \
        : "=r"((R)[0]), "=r"((R)[1]), "=r"((R)[2]), "=r"((R)[3]) : "r"(a))
#define MMA(c, A, b0, b1) \
    asm volatile("mma.sync.aligned.m16n8k16.row.col.f32.bf16.bf16.f32 " \
        "{%0,%1,%2,%3}, {%4,%5,%6,%7}, {%8,%9}, {%0,%1,%2,%3};" \
        : "+f"((c)[0]), "+f"((c)[1]), "+f"((c)[2]), "+f"((c)[3]) \
        : "r"((A)[0]), "r"((A)[1]), "r"((A)[2]), "r"((A)[3]), "r"(b0), "r"(b1))

__device__ __forceinline__ u32 packbf2(float a, float b) {
    u32 r;
    asm("cvt.rn.bf16x2.f32 %0, %1, %2;" : "=r"(r) : "f"(b), "f"(a));  // lo=a hi=b
    return r;
}
__device__ __forceinline__ void split2(float a, float b, u32& h, u32& l) {
    h = packbf2(a, b);
    l = packbf2(a - __uint_as_float(h << 16), b - __uint_as_float(h & 0xFFFF0000u));
}
__device__ __forceinline__ float sigmoidf_(float x) { return 1.f / (1.f + expf(-x)); }
__device__ __forceinline__ float siluf_(float x)    { return __fdividef(x, 1.f + __expf(-x)); }

// ---------------- fp32 -> bf16 hi/lo split ----------------
__global__ void splitk(const float4* __restrict__ in, uint2* __restrict__ oh,
                       uint2* __restrict__ ol, long n4) {
    long i = blockIdx.x * (long)blockDim.x + threadIdx.x;
    long st = (long)gridDim.x * blockDim.x;
    for (; i < n4; i += st) {
        float4 q = in[i];
        u32 h0, l0, h1, l1;
        split2(q.x, q.y, h0, l0);
        split2(q.z, q.w, h1, l1);
        oh[i] = make_uint2(h0, h1);
        ol[i] = make_uint2(l0, l1);
    }
}

// ---------------- gate scores (exact fp32 for stable ranking) ----------------
__global__ void gate_kernel(const float* __restrict__ h, const float* __restrict__ gate_w,
                            float* __restrict__ scoresT, int T) {
    int warp = (int)((blockIdx.x * blockDim.x + threadIdx.x) >> 5);
    int lane = threadIdx.x & 31;
    if (warp >= T) return;
    const float* hr = h + (size_t)warp * DIM;
    float hreg[32];
#pragma unroll
    for (int i = 0; i < 32; i++) hreg[i] = hr[lane + 32 * i];
#pragma unroll
    for (int e = 0; e < NEXP; e++) {
        const float* w = gate_w + e * DIM;
        float s = 0.f;
#pragma unroll
        for (int i = 0; i < 32; i++) s = fmaf(hreg[i], w[lane + 32 * i], s);
#pragma unroll
        for (int o = 16; o; o >>= 1) s += __shfl_xor_sync(0xffffffffu, s, o);
        if (lane == 0) scoresT[e * T + warp] = sigmoidf_(s);
    }
}

// ---------------- exact top-k (matches jax.lax.top_k ties) ----------------
__global__ void topk_kernel(const float* __restrict__ scoresT, int* __restrict__ ids,
                            float* __restrict__ tscore, int T, int cap) {
    extern __shared__ u64 s_keys[];
    int e = blockIdx.x;
    const float* s = scoresT + (size_t)e * T;
    for (int i = threadIdx.x; i < NSORT; i += blockDim.x) {
        float v = (i < T) ? s[i] : -1e30f;
        u32 u = __float_as_uint(v);
        u32 ob = (u & 0x80000000u) ? ~u : (u | 0x80000000u);
        s_keys[i] = ((u64)ob << 32) | (u32)(0xFFFFFFFFu - (u32)i);
    }
    __syncthreads();
    for (u32 k = 2; k <= NSORT; k <<= 1)
        for (u32 j = k >> 1; j > 0; j >>= 1) {
            for (u32 i = threadIdx.x; i < NSORT; i += blockDim.x) {
                u32 ixj = i ^ j;
                if (ixj > i) {
                    u64 a = s_keys[i], b = s_keys[ixj];
                    if (((i & k) == 0) ? (a < b) : (a > b)) { s_keys[i] = b; s_keys[ixj] = a; }
                }
            }
            __syncthreads();
        }
    for (int i = threadIdx.x; i < cap; i += blockDim.x) {
        u32 idx = 0xFFFFFFFFu - (u32)(s_keys[i] & 0xFFFFFFFFull);
        ids[e * cap + i] = (int)idx;
        tscore[e * cap + i] = s[idx];
    }
}

// ========== tensor-core GEMM: C = A@B^T, split-bf16 3-term ==========
// CTA tile 128x64, BK=64, 2-stage cp.async, 2 CTAs/SM (96KB smem).
// EPI 0: silu(acc+bias) -> bf16 hi/lo      1: (acc+bias)*aux -> bf16 hi/lo
//     2: atomicAdd(out[tok], (acc+bias)*score)      3: plain f32 store
struct GArgs {
    const char* Ah; const char* Al; long long aStrE; int K;
    const int* gids; int cap;
    const char* Bh; const char* Bl; long long bStrE;
    const float* bias; long long biasStrE;
    const char* auxH; const char* auxL; long long auxStrE;
    char* oH; char* oL; long long oStrE; int ldo;
    float* oF;
    const float* tsc;
};

// stage: Ah 16KB | Al 16KB | Bh 8KB | Bl 8KB = 48KB; 2 stages = 96KB
#define ST_AL 16384
#define ST_BH 32768
#define ST_BL 40960
#define ST_SZ 49152
#define MM_SMEM (2 * ST_SZ)

template <int EPI>
__global__ __launch_bounds__(256, 2) void mm(GArgs g) {
    extern __shared__ char smem[];
    const u32 sb = smem_u32(smem);
    __shared__ int rows[128];
    const int tid = threadIdx.x, lane = tid & 31, wid = tid >> 5;
    const int e = blockIdx.z, n0 = blockIdx.x * 64, m0 = blockIdx.y * 128;

    if (tid < 128) rows[tid] = (g.gids && EPI != 2) ? g.gids[e * g.cap + m0 + tid] : (m0 + tid);
    __syncthreads();

    // A loads: thread -> row tid>>1, half (tid&1)*64B, 4x16B
    const int ra = tid >> 1, ha = tid & 1;
    const char* pAh = g.Ah + ((size_t)e * g.aStrE + (size_t)rows[ra] * g.K + ha * 32) * 2;
    const char* pAl = g.Al + ((size_t)e * g.aStrE + (size_t)rows[ra] * g.K + ha * 32) * 2;
    u32 dstA[4];
#pragma unroll
    for (int i = 0; i < 4; i++) {
        u32 o = ra * 128 + ha * 64 + i * 16;
        dstA[i] = o ^ ((o >> 3) & 0x70);
    }
    // B loads: thread -> row tid>>2, quarter (tid&3)*32B, 2x16B
    const int rb = tid >> 2, qb = tid & 3;
    const char* pBh = g.Bh + ((size_t)e * g.bStrE + (size_t)(n0 + rb) * g.K + qb * 16) * 2;
    const char* pBl = g.Bl + ((size_t)e * g.bStrE + (size_t)(n0 + rb) * g.K + qb * 16) * 2;
    u32 dstB[2];
#pragma unroll
    for (int i = 0; i < 2; i++) {
        u32 o = rb * 128 + qb * 32 + i * 16;
        dstB[i] = o ^ ((o >> 3) & 0x70);
    }

    // warp tile 32x32: wm = (wid>>1)*32, wn = (wid&1)*32
    const int wm = (wid >> 1) * 32, wn = (wid & 1) * 32;
    const u32 xv = (lane & 7) << 4;
    const u32 hib = (lane >> 4) * 16;
    u32 aoffs[2], boffs[2];
#pragma unroll
    for (int mi = 0; mi < 2; mi++) aoffs[mi] = (wm + mi * 16 + (lane & 15)) * 128;
#pragma unroll
    for (int nh = 0; nh < 2; nh++) boffs[nh] = (wn + nh * 16 + (lane & 15)) * 128;

    float acc[2][4][4];
#pragma unroll
    for (int a = 0; a < 2; a++)
#pragma unroll
        for (int b = 0; b < 4; b++)
#pragma unroll
            for (int c = 0; c < 4; c++) acc[a][b][c] = 0.f;

    auto load_stage = [&](int s, int kt) {
        u32 st = sb + s * ST_SZ;
        size_t kb = (size_t)kt * 128;
#pragma unroll
        for (int i = 0; i < 4; i++) {
            cpa16(st + dstA[i],         pAh + kb + i * 16);
            cpa16(st + ST_AL + dstA[i], pAl + kb + i * 16);
        }
#pragma unroll
        for (int i = 0; i < 2; i++) {
            cpa16(st + ST_BH + dstB[i], pBh + kb + i * 16);
            cpa16(st + ST_BL + dstB[i], pBl + kb + i * 16);
        }
    };

    const int NT = g.K >> 6;
    load_stage(0, 0); CP_COMMIT();

    for (int kt = 0; kt < NT; kt++) {
        if (kt + 1 < NT) { load_stage((kt + 1) & 1, kt + 1); CP_COMMIT(); CP_WAIT1(); }
        else CP_WAIT0();
        __syncthreads();
        const u32 stb = sb + (kt & 1) * ST_SZ;
#pragma unroll
        for (int ks = 0; ks < 4; ks++) {
            const u32 kx = ks * 32 + hib;
            u32 ah[2][4], al[2][4], bhf[2][4], blf[2][4];
#pragma unroll
            for (int mi = 0; mi < 2; mi++) {
                u32 ad = stb + aoffs[mi] + (kx ^ xv);
                LDM4(ah[mi], ad);
                LDM4(al[mi], ad + ST_AL);
            }
#pragma unroll
            for (int nh = 0; nh < 2; nh++) {
                u32 bd = stb + ST_BH + boffs[nh] + (kx ^ xv);
                LDM4(bhf[nh], bd);
                LDM4(blf[nh], bd + 8192);
            }
#pragma unroll
            for (int mi = 0; mi < 2; mi++)
#pragma unroll
                for (int ni = 0; ni < 4; ni++) {
                    const int nh = ni >> 1, o = ni & 1;
                    MMA(acc[mi][ni], ah[mi], bhf[nh][o], bhf[nh][2 + o]);
                    MMA(acc[mi][ni], ah[mi], blf[nh][o], blf[nh][2 + o]);
                    MMA(acc[mi][ni], al[mi], bhf[nh][o], bhf[nh][2 + o]);
                }
        }
        __syncthreads();
    }

    // ---------------- epilogue ----------------
    const float* bias = g.bias ? g.bias + (size_t)e * g.biasStrE : nullptr;
#pragma unroll
    for (int mi = 0; mi < 2; mi++)
#pragma unroll
        for (int ni = 0; ni < 4; ni++) {
            const int lr = wm + mi * 16 + (lane >> 2);
            const int col = wn + ni * 8 + (lane & 3) * 2;
            const int n = n0 + col;
            float b0 = 0.f, b1 = 0.f;
            if (bias) { b0 = bias[n]; b1 = bias[n + 1]; }
            float v[4] = {acc[mi][ni][0] + b0, acc[mi][ni][1] + b1,
                          acc[mi][ni][2] + b0, acc[mi][ni][3] + b1};
            if (EPI == 2) {
#pragma unroll
                for (int hrow = 0; hrow < 2; hrow++) {
                    int sl = e * g.cap + m0 + lr + hrow * 8;
                    int tok = g.gids[sl];
                    float sc = g.tsc[sl];
                    float* orow = g.oF + (size_t)tok * DIM + n;
                    atomicAdd(orow,     v[2 * hrow]     * sc);
                    atomicAdd(orow + 1, v[2 * hrow + 1] * sc);
                }
            } else if (EPI == 3) {
                size_t off = (size_t)(m0 + lr) * g.ldo + n;
                g.oF[off] = v[0]; g.oF[off + 1] = v[1];
                g.oF[off + 8 * g.ldo] = v[2]; g.oF[off + 8 * g.ldo + 1] = v[3];
            } else {
#pragma unroll
                for (int hrow = 0; hrow < 2; hrow++) {
                    size_t off = (size_t)e * g.oStrE + (size_t)(m0 + lr + hrow * 8) * g.ldo + n;
                    float v0 = v[2 * hrow], v1 = v[2 * hrow + 1];
                    if (EPI == 0) { v0 = siluf_(v0); v1 = siluf_(v1); }
                    else {
                        u32 ph = *(const u32*)(g.auxH + ((size_t)e * g.auxStrE +
                                  (size_t)(m0 + lr + hrow * 8) * g.ldo + n) * 2);
                        u32 pl = *(const u32*)(g.auxL + ((size_t)e * g.auxStrE +
                                  (size_t)(m0 + lr + hrow * 8) * g.ldo + n) * 2);
                        float a0 = __uint_as_float(ph << 16) + __uint_as_float(pl << 16);
                        float a1 = __uint_as_float(ph & 0xFFFF0000u) + __uint_as_float(pl & 0xFFFF0000u);
                        v0 *= a0; v1 *= a1;
                    }
                    u32 h, l;
                    split2(v0, v1, h, l);
                    *(u32*)(g.oH + off * 2) = h;
                    *(u32*)(g.oL + off * 2) = l;
                }
            }
        }
}

// ---------------- launch ----------------
extern "C" void kernel_launch(void* const* d_in, const int* in_sizes, int n_in,
                              void* d_out, int out_size) {
    const float* x      = (const float*)d_in[0];
    const float* gate_w = (const float*)d_in[1];
    const float* up_w   = (const float*)d_in[2];
    const float* up_b   = (const float*)d_in[3];
    const float* gw     = (const float*)d_in[4];
    const float* gb     = (const float*)d_in[5];
    const float* down_w = (const float*)d_in[6];
    const float* down_b = (const float*)d_in[7];
    const float* shg    = (const float*)d_in[8];
    const float* shu    = (const float*)d_in[9];
    const float* shd    = (const float*)d_in[10];
    (void)n_in; (void)out_size;
    float* out = (float*)d_out;

    int T = in_sizes[0] / DIM;               // 8192
    int cap = (T * 2 + NEXP - 1) / NEXP;     // 1024

    unsigned char* buf;
    cudaGetSymbolAddress((void**)&buf, g_buf);
    float* scoresT = (float*)(buf + O_SC);
    int*   ids     = (int*)(buf + O_IDS);
    float* tsc     = (float*)(buf + O_TSC);

    static bool s_init = false;
    if (!s_init) {
        s_init = true;
        cudaFuncSetAttribute(topk_kernel, cudaFuncAttributeMaxDynamicSharedMemorySize,
                             NSORT * (int)sizeof(u64));
        cudaFuncSetAttribute(mm<0>, cudaFuncAttributeMaxDynamicSharedMemorySize, MM_SMEM);
        cudaFuncSetAttribute(mm<1>, cudaFuncAttributeMaxDynamicSharedMemorySize, MM_SMEM);
        cudaFuncSetAttribute(mm<2>, cudaFuncAttributeMaxDynamicSharedMemorySize, MM_SMEM);
        cudaFuncSetAttribute(mm<3>, cudaFuncAttributeMaxDynamicSharedMemorySize, MM_SMEM);
    }

    // 1) splits
    splitk<<<1024, 256>>>((const float4*)x, (uint2*)(buf + O_XH), (uint2*)(buf + O_XL),
                          (long)((size_t)T * DIM / 4));
    long w4 = (long)((size_t)NEXP * FDIM * DIM / 4);
    splitk<<<4096, 256>>>((const float4*)gw,     (uint2*)(buf + O_WGH), (uint2*)(buf + O_WGL), w4);
    splitk<<<4096, 256>>>((const float4*)up_w,   (uint2*)(buf + O_WUH), (uint2*)(buf + O_WUL), w4);
    splitk<<<4096, 256>>>((const float4*)down_w, (uint2*)(buf + O_WDH), (uint2*)(buf + O_WDL), w4);
    long s4 = (long)((size_t)SHDIM * DIM / 4);
    splitk<<<512, 256>>>((const float4*)shg, (uint2*)(buf + O_SGH), (uint2*)(buf + O_SGL), s4);
    splitk<<<512, 256>>>((const float4*)shu, (uint2*)(buf + O_SUH), (uint2*)(buf + O_SUL), s4);
    splitk<<<512, 256>>>((const float4*)shd, (uint2*)(buf + O_SDH), (uint2*)(buf + O_SDL), s4);

    // 2) gate + top-k
    gate_kernel<<<(T + 7) / 8, 256>>>(x, gate_w, scoresT, T);
    topk_kernel<<<NEXP, 1024, NSORT * (int)sizeof(u64)>>>(scoresT, ids, tsc, T, cap);

    GArgs a{};
    // 3) shared gate: silu(x@shg^T) -> SSH/SSL
    a = GArgs{};
    a.Ah = (char*)(buf + O_XH); a.Al = (char*)(buf + O_XL); a.aStrE = 0; a.K = DIM;
    a.Bh = (char*)(buf + O_SGH); a.Bl = (char*)(buf + O_SGL); a.bStrE = 0;
    a.oH = (char*)(buf + O_SSH); a.oL = (char*)(buf + O_SSL); a.oStrE = 0; a.ldo = SHDIM;
    mm<0><<<dim3(SHDIM / 64, T / 128, 1), 256, MM_SMEM>>>(a);

    // 4) shared up: (x@shu^T) * silu -> SAH/SAL
    a.Bh = (char*)(buf + O_SUH); a.Bl = (char*)(buf + O_SUL);
    a.auxH = (char*)(buf + O_SSH); a.auxL = (char*)(buf + O_SSL); a.auxStrE = 0;
    a.oH = (char*)(buf + O_SAH); a.oL = (char*)(buf + O_SAL);
    mm<1><<<dim3(SHDIM / 64, T / 128, 1), 256, MM_SMEM>>>(a);

    // 5) shared down -> out (plain f32 store initializes out)
    a = GArgs{};
    a.Ah = (char*)(buf + O_SAH); a.Al = (char*)(buf + O_SAL); a.aStrE = 0; a.K = SHDIM;
    a.Bh = (char*)(buf + O_SDH); a.Bl = (char*)(buf + O_SDL); a.bStrE = 0;
    a.oF = out; a.ldo = DIM;
    mm<3><<<dim3(DIM / 64, T / 128, 1), 256, MM_SMEM>>>(a);

    // 6) expert gate: silu(x[ids]@gw^T + gb) -> EGH/EGL
    a = GArgs{};
    a.Ah = (char*)(buf + O_XH); a.Al = (char*)(buf + O_XL); a.aStrE = 0; a.K = DIM;
    a.gids = ids; a.cap = cap;
    a.Bh = (char*)(buf + O_WGH); a.Bl = (char*)(buf + O_WGL); a.bStrE = (long long)FDIM * DIM;
    a.bias = gb; a.biasStrE = FDIM;
    a.oH = (char*)(buf + O_EGH); a.oL = (char*)(buf + O_EGL);
    a.oStrE = (long long)cap * FDIM; a.ldo = FDIM;
    mm<0><<<dim3(FDIM / 64, cap / 128, NEXP), 256, MM_SMEM>>>(a);

    // 7) expert up: (x[ids]@up_w^T + up_b) * silu -> EAH/EAL
    a.Bh = (char*)(buf + O_WUH); a.Bl = (char*)(buf + O_WUL);
    a.bias = up_b;
    a.auxH = (char*)(buf + O_EGH); a.auxL = (char*)(buf + O_EGL);
    a.auxStrE = (long long)cap * FDIM;
    a.oH = (char*)(buf + O_EAH); a.oL = (char*)(buf + O_EAL);
    mm<1><<<dim3(FDIM / 64, cap / 128, NEXP), 256, MM_SMEM>>>(a);

    // 8) expert down + weighted scatter-add
    a = GArgs{};
    a.Ah = (char*)(buf + O_EAH); a.Al = (char*)(buf + O_EAL);
    a.aStrE = (long long)cap * FDIM; a.K = FDIM;
    a.gids = ids; a.cap = cap; a.tsc = tsc;
    a.Bh = (char*)(buf + O_WDH); a.Bl = (char*)(buf + O_WDL); a.bStrE = (long long)DIM * FDIM;
    a.bias = down_b; a.biasStrE = DIM;
    a.oF = out; a.ldo = DIM;
    mm<2><<<dim3(DIM / 64, cap / 128, NEXP), 256, MM_SMEM>>>(a);
}

// round 8
// speedup vs baseline: 2.6217x; 1.4828x over previous
#include <cuda_runtime.h>
#include <cuda_fp16.h>
#include <math.h>
#include <stdint.h>

typedef unsigned int u32;
typedef unsigned long long u64;

#define NEXP 16
#define DIM 1024
#define FDIM 4096
#define SHDIM 2048
#define MAXT 8192
#define NSORT 8192
#define MAXCAP 1024

// ---------------- static scratch (fp16 operands) ----------------
constexpr size_t SZ_X  = (size_t)MAXT * DIM * 2;
constexpr size_t SZ_W  = (size_t)NEXP * FDIM * DIM * 2;
constexpr size_t SZ_SW = (size_t)SHDIM * DIM * 2;
constexpr size_t SZ_EA = (size_t)NEXP * MAXCAP * FDIM * 2;
constexpr size_t SZ_SA = (size_t)MAXT * SHDIM * 2;
constexpr size_t O_XH = 0,              O_XL = O_XH + SZ_X;
constexpr size_t O_WG = O_XL + SZ_X,    O_WU = O_WG + SZ_W;
constexpr size_t O_WD = O_WU + SZ_W;
constexpr size_t O_SG = O_WD + SZ_W,    O_SU = O_SG + SZ_SW;
constexpr size_t O_SD = O_SU + SZ_SW;
constexpr size_t O_EGH = O_SD + SZ_SW,  O_EGL = O_EGH + SZ_EA;  // expert silu(gate)
constexpr size_t O_EAH = O_EGL + SZ_EA, O_EAL = O_EAH + SZ_EA;  // expert act
constexpr size_t O_SSH = O_EAL + SZ_EA, O_SSL = O_SSH + SZ_SA;  // shared silu(gate)
constexpr size_t O_SAH = O_SSL + SZ_SA, O_SAL = O_SAH + SZ_SA;  // shared act
constexpr size_t O_SC  = O_SAL + SZ_SA;
constexpr size_t O_IDS = O_SC + (size_t)NEXP * MAXT * 4;
constexpr size_t O_TSC = O_IDS + (size_t)NEXP * MAXCAP * 4;
constexpr size_t TOTAL = O_TSC + (size_t)NEXP * MAXCAP * 4;
__device__ __align__(1024) unsigned char g_buf[TOTAL];

// ---------------- helpers ----------------
__device__ __forceinline__ u32 smem_u32(const void* p) {
    u32 a;
    asm("{ .reg .u64 t; cvta.to.shared.u64 t, %1; cvt.u32.u64 %0, t; }" : "=r"(a) : "l"(p));
    return a;
}
__device__ __forceinline__ void cpa16(u32 dst, const void* src) {
    asm volatile("cp.async.cg.shared.global [%0], [%1], 16;" :: "r"(dst), "l"(src) : "memory");
}
#define CP_COMMIT() asm volatile("cp.async.commit_group;" ::: "memory")
#define CP_WAIT1()  asm volatile("cp.async.wait_group 1;" ::: "memory")
#define CP_WAIT0()  asm volatile("cp.async.wait_group 0;" ::: "memory")
#define LDM4(R, a) \
    asm volatile("ldmatrix.sync.aligned.m8n8.x4.shared.b16 {%0,%1,%2,%3}, [%4];" \
        : "=r"((R)[0]), "=r"((R)[1]), "=r"((R)[2]), "=r"((R)[3]) : "r"(a))
#define MMA(c, A, b0, b1) \
    asm volatile("mma.sync.aligned.m16n8k16.row.col.f32.f16.f16.f32 " \
        "{%0,%1,%2,%3}, {%4,%5,%6,%7}, {%8,%9}, {%0,%1,%2,%3};" \
        : "+f"((c)[0]), "+f"((c)[1]), "+f"((c)[2]), "+f"((c)[3]) \
        : "r"((A)[0]), "r"((A)[1]), "r"((A)[2]), "r"((A)[3]), "r"(b0), "r"(b1))

__device__ __forceinline__ u32 packh2(float a, float b) {
    __half2 h = __floats2half2_rn(a, b);
    return *reinterpret_cast<u32*>(&h);
}
__device__ __forceinline__ float2 unpackh2(u32 v) {
    __half2 h = *reinterpret_cast<__half2*>(&v);
    return __half22float2(h);
}
__device__ __forceinline__ void splith2(float a, float b, u32& h, u32& l) {
    h = packh2(a, b);
    float2 f = unpackh2(h);
    l = packh2(a - f.x, b - f.y);
}
__device__ __forceinline__ float sigmoidf_(float x) { return 1.f / (1.f + expf(-x)); }
__device__ __forceinline__ float siluf_(float x)    { return __fdividef(x, 1.f + __expf(-x)); }

// ---------------- fp32 -> fp16 hi/lo split (activations) ----------------
__global__ void splitk(const float4* __restrict__ in, uint2* __restrict__ oh,
                       uint2* __restrict__ ol, long n4) {
    long i = blockIdx.x * (long)blockDim.x + threadIdx.x;
    long st = (long)gridDim.x * blockDim.x;
    for (; i < n4; i += st) {
        float4 q = in[i];
        u32 h0, l0, h1, l1;
        splith2(q.x, q.y, h0, l0);
        splith2(q.z, q.w, h1, l1);
        oh[i] = make_uint2(h0, h1);
        ol[i] = make_uint2(l0, l1);
    }
}
// ---------------- fp32 -> fp16 convert (weights, 1 term) ----------------
__global__ void cvtk(const float4* __restrict__ in, uint2* __restrict__ oh, long n4) {
    long i = blockIdx.x * (long)blockDim.x + threadIdx.x;
    long st = (long)gridDim.x * blockDim.x;
    for (; i < n4; i += st) {
        float4 q = in[i];
        oh[i] = make_uint2(packh2(q.x, q.y), packh2(q.z, q.w));
    }
}

// ---------------- gate scores (exact fp32 for stable ranking) ----------------
__global__ void gate_kernel(const float* __restrict__ h, const float* __restrict__ gate_w,
                            float* __restrict__ scoresT, int T) {
    int warp = (int)((blockIdx.x * blockDim.x + threadIdx.x) >> 5);
    int lane = threadIdx.x & 31;
    if (warp >= T) return;
    const float* hr = h + (size_t)warp * DIM;
    float hreg[32];
#pragma unroll
    for (int i = 0; i < 32; i++) hreg[i] = hr[lane + 32 * i];
#pragma unroll
    for (int e = 0; e < NEXP; e++) {
        const float* w = gate_w + e * DIM;
        float s = 0.f;
#pragma unroll
        for (int i = 0; i < 32; i++) s = fmaf(hreg[i], w[lane + 32 * i], s);
#pragma unroll
        for (int o = 16; o; o >>= 1) s += __shfl_xor_sync(0xffffffffu, s, o);
        if (lane == 0) scoresT[e * T + warp] = sigmoidf_(s);
    }
}

// ---------------- exact top-k (matches jax.lax.top_k ties) ----------------
__global__ void topk_kernel(const float* __restrict__ scoresT, int* __restrict__ ids,
                            float* __restrict__ tscore, int T, int cap) {
    extern __shared__ u64 s_keys[];
    int e = blockIdx.x;
    const float* s = scoresT + (size_t)e * T;
    for (int i = threadIdx.x; i < NSORT; i += blockDim.x) {
        float v = (i < T) ? s[i] : -1e30f;
        u32 u = __float_as_uint(v);
        u32 ob = (u & 0x80000000u) ? ~u : (u | 0x80000000u);
        s_keys[i] = ((u64)ob << 32) | (u32)(0xFFFFFFFFu - (u32)i);
    }
    __syncthreads();
    for (u32 k = 2; k <= NSORT; k <<= 1)
        for (u32 j = k >> 1; j > 0; j >>= 1) {
            for (u32 i = threadIdx.x; i < NSORT; i += blockDim.x) {
                u32 ixj = i ^ j;
                if (ixj > i) {
                    u64 a = s_keys[i], b = s_keys[ixj];
                    if (((i & k) == 0) ? (a < b) : (a > b)) { s_keys[i] = b; s_keys[ixj] = a; }
                }
            }
            __syncthreads();
        }
    for (int i = threadIdx.x; i < cap; i += blockDim.x) {
        u32 idx = 0xFFFFFFFFu - (u32)(s_keys[i] & 0xFFFFFFFFull);
        ids[e * cap + i] = (int)idx;
        tscore[e * cap + i] = s[idx];
    }
}

// ========== tensor-core GEMM: C = A@B^T, fp16 asymmetric 2-term ==========
// A = ah+al (fp16 split), B = bh (fp16). 2 MMAs per k16 per acc tile.
// CTA tile 128x128, BK=64, 2-stage cp.async, 2 CTAs/SM (96KB smem).
// EPI 0: silu(acc+bias) -> fp16 hi/lo      1: (acc+bias)*aux -> fp16 hi/lo
//     2: atomicAdd(out[tok], (acc+bias)*score)      3: plain f32 store
struct GArgs {
    const char* Ah; const char* Al; long long aStrE; int K;
    const int* gids; int cap;
    const char* Bh; long long bStrE;
    const float* bias; long long biasStrE;
    const char* auxH; const char* auxL; long long auxStrE;
    char* oH; char* oL; long long oStrE; int ldo;
    float* oF;
    const float* tsc;
};

// stage: Ah 16KB | Al 16KB | Bh 16KB = 48KB; 2 stages = 96KB
#define ST_AL 16384
#define ST_BH 32768
#define ST_SZ 49152
#define MM_SMEM (2 * ST_SZ)

template <int EPI>
__global__ __launch_bounds__(256, 2) void mm(GArgs g) {
    extern __shared__ char smem[];
    const u32 sb = smem_u32(smem);
    __shared__ int rows[128];
    const int tid = threadIdx.x, lane = tid & 31, wid = tid >> 5;
    const int e = blockIdx.z, n0 = blockIdx.x * 128, m0 = blockIdx.y * 128;

    if (tid < 128) rows[tid] = (g.gids && EPI != 2) ? g.gids[e * g.cap + m0 + tid] : (m0 + tid);
    __syncthreads();

    // loads: thread -> row tid>>1, half (tid&1)*64B, 4x16B per tensor
    const int ra = tid >> 1, ha = tid & 1;
    const char* pAh = g.Ah + ((size_t)e * g.aStrE + (size_t)rows[ra] * g.K + ha * 32) * 2;
    const char* pAl = g.Al + ((size_t)e * g.aStrE + (size_t)rows[ra] * g.K + ha * 32) * 2;
    const char* pBh = g.Bh + ((size_t)e * g.bStrE + (size_t)(n0 + ra) * g.K + ha * 32) * 2;
    u32 dstA[4];
#pragma unroll
    for (int i = 0; i < 4; i++) {
        u32 o = ra * 128 + ha * 64 + i * 16;
        dstA[i] = o ^ ((o >> 3) & 0x70);
    }

    // warp tile 32(M) x 64(N): wm = (wid>>1)*32, wn = (wid&1)*64
    const int wm = (wid >> 1) * 32, wn = (wid & 1) * 64;
    const u32 xv = (lane & 7) << 4;
    const u32 hib = (lane >> 4) * 16;
    u32 aoffs[2], boffs[4];
#pragma unroll
    for (int mi = 0; mi < 2; mi++) aoffs[mi] = (wm + mi * 16 + (lane & 15)) * 128;
#pragma unroll
    for (int nj = 0; nj < 4; nj++) boffs[nj] = (wn + nj * 16 + (lane & 15)) * 128;

    float acc[2][8][4];
#pragma unroll
    for (int a = 0; a < 2; a++)
#pragma unroll
        for (int b = 0; b < 8; b++)
#pragma unroll
            for (int c = 0; c < 4; c++) acc[a][b][c] = 0.f;

    auto load_stage = [&](int s, int kt) {
        u32 st = sb + s * ST_SZ;
        size_t kb = (size_t)kt * 128;
#pragma unroll
        for (int i = 0; i < 4; i++) {
            cpa16(st + dstA[i],         pAh + kb + i * 16);
            cpa16(st + ST_AL + dstA[i], pAl + kb + i * 16);
            cpa16(st + ST_BH + dstA[i], pBh + kb + i * 16);
        }
    };

    const int NT = g.K >> 6;
    load_stage(0, 0); CP_COMMIT();

    for (int kt = 0; kt < NT; kt++) {
        if (kt + 1 < NT) { load_stage((kt + 1) & 1, kt + 1); CP_COMMIT(); CP_WAIT1(); }
        else CP_WAIT0();
        __syncthreads();
        const u32 stb = sb + (kt & 1) * ST_SZ;
#pragma unroll
        for (int ks = 0; ks < 4; ks++) {
            const u32 kx = ks * 32 + hib;
            u32 ah[2][4], al[2][4], bf[4][4];
#pragma unroll
            for (int mi = 0; mi < 2; mi++) {
                u32 ad = stb + aoffs[mi] + (kx ^ xv);
                LDM4(ah[mi], ad);
                LDM4(al[mi], ad + ST_AL);
            }
#pragma unroll
            for (int nj = 0; nj < 4; nj++)
                LDM4(bf[nj], stb + ST_BH + boffs[nj] + (kx ^ xv));
#pragma unroll
            for (int mi = 0; mi < 2; mi++)
#pragma unroll
                for (int nj = 0; nj < 4; nj++)
#pragma unroll
                    for (int o = 0; o < 2; o++) {
                        MMA(acc[mi][nj * 2 + o], ah[mi], bf[nj][o], bf[nj][2 + o]);
                        MMA(acc[mi][nj * 2 + o], al[mi], bf[nj][o], bf[nj][2 + o]);
                    }
        }
        __syncthreads();
    }

    // ---------------- epilogue ----------------
    const float* bias = g.bias ? g.bias + (size_t)e * g.biasStrE : nullptr;
#pragma unroll
    for (int mi = 0; mi < 2; mi++)
#pragma unroll
        for (int ni = 0; ni < 8; ni++) {
            const int lr = wm + mi * 16 + (lane >> 2);
            const int col = wn + ni * 8 + (lane & 3) * 2;
            const int n = n0 + col;
            float b0 = 0.f, b1 = 0.f;
            if (bias) { b0 = bias[n]; b1 = bias[n + 1]; }
            float v[4] = {acc[mi][ni][0] + b0, acc[mi][ni][1] + b1,
                          acc[mi][ni][2] + b0, acc[mi][ni][3] + b1};
            if (EPI == 2) {
#pragma unroll
                for (int hrow = 0; hrow < 2; hrow++) {
                    int sl = e * g.cap + m0 + lr + hrow * 8;
                    int tok = g.gids[sl];
                    float sc = g.tsc[sl];
                    float* orow = g.oF + (size_t)tok * DIM + n;
                    atomicAdd(orow,     v[2 * hrow]     * sc);
                    atomicAdd(orow + 1, v[2 * hrow + 1] * sc);
                }
            } else if (EPI == 3) {
                size_t off = (size_t)(m0 + lr) * g.ldo + n;
                g.oF[off] = v[0]; g.oF[off + 1] = v[1];
                g.oF[off + 8 * g.ldo] = v[2]; g.oF[off + 8 * g.ldo + 1] = v[3];
            } else {
#pragma unroll
                for (int hrow = 0; hrow < 2; hrow++) {
                    size_t off = (size_t)e * g.oStrE + (size_t)(m0 + lr + hrow * 8) * g.ldo + n;
                    float v0 = v[2 * hrow], v1 = v[2 * hrow + 1];
                    if (EPI == 0) { v0 = siluf_(v0); v1 = siluf_(v1); }
                    else {
                        size_t aoff = ((size_t)e * g.auxStrE +
                                       (size_t)(m0 + lr + hrow * 8) * g.ldo + n) * 2;
                        float2 xh = unpackh2(*(const u32*)(g.auxH + aoff));
                        float2 xl = unpackh2(*(const u32*)(g.auxL + aoff));
                        v0 *= (xh.x + xl.x);
                        v1 *= (xh.y + xl.y);
                    }
                    u32 h, l;
                    splith2(v0, v1, h, l);
                    *(u32*)(g.oH + off * 2) = h;
                    *(u32*)(g.oL + off * 2) = l;
                }
            }
        }
}

// ---------------- launch ----------------
extern "C" void kernel_launch(void* const* d_in, const int* in_sizes, int n_in,
                              void* d_out, int out_size) {
    const float* x      = (const float*)d_in[0];
    const float* gate_w = (const float*)d_in[1];
    const float* up_w   = (const float*)d_in[2];
    const float* up_b   = (const float*)d_in[3];
    const float* gw     = (const float*)d_in[4];
    const float* gb     = (const float*)d_in[5];
    const float* down_w = (const float*)d_in[6];
    const float* down_b = (const float*)d_in[7];
    const float* shg    = (const float*)d_in[8];
    const float* shu    = (const float*)d_in[9];
    const float* shd    = (const float*)d_in[10];
    (void)n_in; (void)out_size;
    float* out = (float*)d_out;

    int T = in_sizes[0] / DIM;               // 8192
    int cap = (T * 2 + NEXP - 1) / NEXP;     // 1024

    unsigned char* buf;
    cudaGetSymbolAddress((void**)&buf, g_buf);
    float* scoresT = (float*)(buf + O_SC);
    int*   ids     = (int*)(buf + O_IDS);
    float* tsc     = (float*)(buf + O_TSC);

    static bool s_init = false;
    if (!s_init) {
        s_init = true;
        cudaFuncSetAttribute(topk_kernel, cudaFuncAttributeMaxDynamicSharedMemorySize,
                             NSORT * (int)sizeof(u64));
        cudaFuncSetAttribute(mm<0>, cudaFuncAttributeMaxDynamicSharedMemorySize, MM_SMEM);
        cudaFuncSetAttribute(mm<1>, cudaFuncAttributeMaxDynamicSharedMemorySize, MM_SMEM);
        cudaFuncSetAttribute(mm<2>, cudaFuncAttributeMaxDynamicSharedMemorySize, MM_SMEM);
        cudaFuncSetAttribute(mm<3>, cudaFuncAttributeMaxDynamicSharedMemorySize, MM_SMEM);
    }

    long w4 = (long)((size_t)NEXP * FDIM * DIM / 4);
    long s4 = (long)((size_t)SHDIM * DIM / 4);

    // ordered so the 6th launch (ncu -s 5 -c 1) is an mm kernel
    splitk<<<1024, 256>>>((const float4*)x, (uint2*)(buf + O_XH), (uint2*)(buf + O_XL),
                          (long)((size_t)T * DIM / 4));                          // 1
    gate_kernel<<<(T + 7) / 8, 256>>>(x, gate_w, scoresT, T);                    // 2
    topk_kernel<<<NEXP, 1024, NSORT * (int)sizeof(u64)>>>(scoresT, ids, tsc, T, cap); // 3
    cvtk<<<512, 256>>>((const float4*)shg, (uint2*)(buf + O_SG), s4);            // 4
    cvtk<<<512, 256>>>((const float4*)shu, (uint2*)(buf + O_SU), s4);            // 5

    GArgs a{};
    // 6) shared gate: silu(x@shg^T) -> SSH/SSL       <-- profiled launch
    a = GArgs{};
    a.Ah = (char*)(buf + O_XH); a.Al = (char*)(buf + O_XL); a.aStrE = 0; a.K = DIM;
    a.Bh = (char*)(buf + O_SG); a.bStrE = 0;
    a.oH = (char*)(buf + O_SSH); a.oL = (char*)(buf + O_SSL); a.oStrE = 0; a.ldo = SHDIM;
    mm<0><<<dim3(SHDIM / 128, T / 128, 1), 256, MM_SMEM>>>(a);

    cvtk<<<512, 256>>>((const float4*)shd, (uint2*)(buf + O_SD), s4);            // 7

    // 8) shared up: (x@shu^T) * silu -> SAH/SAL
    a.Bh = (char*)(buf + O_SU);
    a.auxH = (char*)(buf + O_SSH); a.auxL = (char*)(buf + O_SSL); a.auxStrE = 0;
    a.oH = (char*)(buf + O_SAH); a.oL = (char*)(buf + O_SAL);
    mm<1><<<dim3(SHDIM / 128, T / 128, 1), 256, MM_SMEM>>>(a);

    // 9) shared down -> out (plain f32 store initializes out)
    a = GArgs{};
    a.Ah = (char*)(buf + O_SAH); a.Al = (char*)(buf + O_SAL); a.aStrE = 0; a.K = SHDIM;
    a.Bh = (char*)(buf + O_SD); a.bStrE = 0;
    a.oF = out; a.ldo = DIM;
    mm<3><<<dim3(DIM / 128, T / 128, 1), 256, MM_SMEM>>>(a);

    cvtk<<<4096, 256>>>((const float4*)gw,   (uint2*)(buf + O_WG), w4);          // 10
    cvtk<<<4096, 256>>>((const float4*)up_w, (uint2*)(buf + O_WU), w4);          // 11

    // 12) expert gate: silu(x[ids]@gw^T + gb) -> EGH/EGL
    a = GArgs{};
    a.Ah = (char*)(buf + O_XH); a.Al = (char*)(buf + O_XL); a.aStrE = 0; a.K = DIM;
    a.gids = ids; a.cap = cap;
    a.Bh = (char*)(buf + O_WG); a.bStrE = (long long)FDIM * DIM;
    a.bias = gb; a.biasStrE = FDIM;
    a.oH = (char*)(buf + O_EGH); a.oL = (char*)(buf + O_EGL);
    a.oStrE = (long long)cap * FDIM; a.ldo = FDIM;
    mm<0><<<dim3(FDIM / 128, cap / 128, NEXP), 256, MM_SMEM>>>(a);

    // 13) expert up: (x[ids]@up_w^T + up_b) * silu -> EAH/EAL
    a.Bh = (char*)(buf + O_WU);
    a.bias = up_b;
    a.auxH = (char*)(buf + O_EGH); a.auxL = (char*)(buf + O_EGL);
    a.auxStrE = (long long)cap * FDIM;
    a.oH = (char*)(buf + O_EAH); a.oL = (char*)(buf + O_EAL);
    mm<1><<<dim3(FDIM / 128, cap / 128, NEXP), 256, MM_SMEM>>>(a);

    cvtk<<<4096, 256>>>((const float4*)down_w, (uint2*)(buf + O_WD), w4);        // 14

    // 15) expert down + weighted scatter-add
    a = GArgs{};
    a.Ah = (char*)(buf + O_EAH); a.Al = (char*)(buf + O_EAL);
    a.aStrE = (long long)cap * FDIM; a.K = FDIM;
    a.gids = ids; a.cap = cap; a.tsc = tsc;
    a.Bh = (char*)(buf + O_WD); a.bStrE = (long long)DIM * FDIM;
    a.bias = down_b; a.biasStrE = DIM;
    a.oF = out; a.ldo = DIM;
    mm<2><<<dim3(DIM / 128, cap / 128, NEXP), 256, MM_SMEM>>>(a);
}

// round 9
// speedup vs baseline: 4.1366x; 1.5778x over previous
#include <cuda_runtime.h>
#include <cuda_fp16.h>
#include <math.h>
#include <stdint.h>

typedef unsigned int u32;
typedef unsigned long long u64;

#define NEXP 16
#define DIM 1024
#define FDIM 4096
#define SHDIM 2048
#define MAXT 8192
#define NSORT 8192
#define MAXCAP 1024

// ---------------- static scratch (fp16 operands) ----------------
constexpr size_t SZ_X  = (size_t)MAXT * DIM * 2;
constexpr size_t SZ_W  = (size_t)NEXP * FDIM * DIM * 2;
constexpr size_t SZ_SW = (size_t)SHDIM * DIM * 2;
constexpr size_t SZ_EA = (size_t)NEXP * MAXCAP * FDIM * 2;
constexpr size_t SZ_SA = (size_t)MAXT * SHDIM * 2;
constexpr size_t O_X  = 0;
constexpr size_t O_WG = O_X + SZ_X,     O_WU = O_WG + SZ_W;
constexpr size_t O_WD = O_WU + SZ_W;
constexpr size_t O_SG = O_WD + SZ_W,    O_SU = O_SG + SZ_SW;
constexpr size_t O_SD = O_SU + SZ_SW;
constexpr size_t O_EGH = O_SD + SZ_SW,  O_EGL = O_EGH + SZ_EA;  // expert silu(gate) hi/lo
constexpr size_t O_EAH = O_EGL + SZ_EA;                          // expert act (single)
constexpr size_t O_SSH = O_EAH + SZ_EA, O_SSL = O_SSH + SZ_SA;  // shared silu(gate) hi/lo
constexpr size_t O_SAH = O_SSL + SZ_SA;                          // shared act (single)
constexpr size_t O_SC  = O_SAH + SZ_SA;
constexpr size_t O_IDS = O_SC + (size_t)NEXP * MAXT * 4;
constexpr size_t O_TSC = O_IDS + (size_t)NEXP * MAXCAP * 4;
constexpr size_t TOTAL = O_TSC + (size_t)NEXP * MAXCAP * 4;
__device__ __align__(1024) unsigned char g_buf[TOTAL];

// ---------------- helpers ----------------
__device__ __forceinline__ u32 smem_u32(const void* p) {
    u32 a;
    asm("{ .reg .u64 t; cvta.to.shared.u64 t, %1; cvt.u32.u64 %0, t; }" : "=r"(a) : "l"(p));
    return a;
}
__device__ __forceinline__ void cpa16(u32 dst, const void* src) {
    asm volatile("cp.async.cg.shared.global [%0], [%1], 16;" :: "r"(dst), "l"(src) : "memory");
}
#define CP_COMMIT() asm volatile("cp.async.commit_group;" ::: "memory")
#define CP_WAIT2()  asm volatile("cp.async.wait_group 2;" ::: "memory")
#define CP_WAIT1()  asm volatile("cp.async.wait_group 1;" ::: "memory")
#define CP_WAIT0()  asm volatile("cp.async.wait_group 0;" ::: "memory")
#define LDM4(R, a) \
    asm volatile("ldmatrix.sync.aligned.m8n8.x4.shared.b16 {%0,%1,%2,%3}, [%4];" \
        : "=r"((R)[0]), "=r"((R)[1]), "=r"((R)[2]), "=r"((R)[3]) : "r"(a))
#define MMA(c, A, b0, b1) \
    asm volatile("mma.sync.aligned.m16n8k16.row.col.f32.f16.f16.f32 " \
        "{%0,%1,%2,%3}, {%4,%5,%6,%7}, {%8,%9}, {%0,%1,%2,%3};" \
        : "+f"((c)[0]), "+f"((c)[1]), "+f"((c)[2]), "+f"((c)[3]) \
        : "r"((A)[0]), "r"((A)[1]), "r"((A)[2]), "r"((A)[3]), "r"(b0), "r"(b1))

__device__ __forceinline__ u32 packh2(float a, float b) {
    __half2 h = __floats2half2_rn(a, b);
    return *reinterpret_cast<u32*>(&h);
}
__device__ __forceinline__ float2 unpackh2(u32 v) {
    __half2 h = *reinterpret_cast<__half2*>(&v);
    return __half22float2(h);
}
__device__ __forceinline__ void splith2(float a, float b, u32& h, u32& l) {
    h = packh2(a, b);
    float2 f = unpackh2(h);
    l = packh2(a - f.x, b - f.y);
}
__device__ __forceinline__ float sigmoidf_(float x) { return 1.f / (1.f + expf(-x)); }
__device__ __forceinline__ float siluf_(float x)    { return __fdividef(x, 1.f + __expf(-x)); }

// ---------------- fp32 -> fp16 convert ----------------
__global__ void cvtk(const float4* __restrict__ in, uint2* __restrict__ oh, long n4) {
    long i = blockIdx.x * (long)blockDim.x + threadIdx.x;
    long st = (long)gridDim.x * blockDim.x;
    for (; i < n4; i += st) {
        float4 q = in[i];
        oh[i] = make_uint2(packh2(q.x, q.y), packh2(q.z, q.w));
    }
}

// ---------------- gate scores (exact fp32 for stable ranking) ----------------
__global__ void gate_kernel(const float* __restrict__ h, const float* __restrict__ gate_w,
                            float* __restrict__ scoresT, int T) {
    int warp = (int)((blockIdx.x * blockDim.x + threadIdx.x) >> 5);
    int lane = threadIdx.x & 31;
    if (warp >= T) return;
    const float* hr = h + (size_t)warp * DIM;
    float hreg[32];
#pragma unroll
    for (int i = 0; i < 32; i++) hreg[i] = hr[lane + 32 * i];
#pragma unroll
    for (int e = 0; e < NEXP; e++) {
        const float* w = gate_w + e * DIM;
        float s = 0.f;
#pragma unroll
        for (int i = 0; i < 32; i++) s = fmaf(hreg[i], w[lane + 32 * i], s);
#pragma unroll
        for (int o = 16; o; o >>= 1) s += __shfl_xor_sync(0xffffffffu, s, o);
        if (lane == 0) scoresT[e * T + warp] = sigmoidf_(s);
    }
}

// ---------------- exact top-k (matches jax.lax.top_k ties) ----------------
__global__ void topk_kernel(const float* __restrict__ scoresT, int* __restrict__ ids,
                            float* __restrict__ tscore, int T, int cap) {
    extern __shared__ u64 s_keys[];
    int e = blockIdx.x;
    const float* s = scoresT + (size_t)e * T;
    for (int i = threadIdx.x; i < NSORT; i += blockDim.x) {
        float v = (i < T) ? s[i] : -1e30f;
        u32 u = __float_as_uint(v);
        u32 ob = (u & 0x80000000u) ? ~u : (u | 0x80000000u);
        s_keys[i] = ((u64)ob << 32) | (u32)(0xFFFFFFFFu - (u32)i);
    }
    __syncthreads();
    for (u32 k = 2; k <= NSORT; k <<= 1)
        for (u32 j = k >> 1; j > 0; j >>= 1) {
            for (u32 i = threadIdx.x; i < NSORT; i += blockDim.x) {
                u32 ixj = i ^ j;
                if (ixj > i) {
                    u64 a = s_keys[i], b = s_keys[ixj];
                    if (((i & k) == 0) ? (a < b) : (a > b)) { s_keys[i] = b; s_keys[ixj] = a; }
                }
            }
            __syncthreads();
        }
    for (int i = threadIdx.x; i < cap; i += blockDim.x) {
        u32 idx = 0xFFFFFFFFu - (u32)(s_keys[i] & 0xFFFFFFFFull);
        ids[e * cap + i] = (int)idx;
        tscore[e * cap + i] = s[idx];
    }
}

// ========== tensor-core GEMM: C = A@B^T, single-term fp16 ==========
// CTA tile 128x128, BK=64, 3-stage cp.async, 2 CTAs/SM (96KB smem).
// EPI 0: silu(acc+bias) -> fp16 hi/lo  (exact pair for later GLU multiply)
//     1: (acc+bias)*(auxH+auxL) -> fp16 single
//     2: atomicAdd(out[tok], (acc+bias)*score)
//     3: plain f32 store
struct GArgs {
    const char* Ah; long long aStrE; int K;
    const int* gids; int cap;
    const char* Bh; long long bStrE;
    const float* bias; long long biasStrE;
    const char* auxH; const char* auxL; long long auxStrE;
    char* oH; char* oL; long long oStrE; int ldo;
    float* oF;
    const float* tsc;
};

// stage: Ah 16KB | Bh 16KB = 32KB; 3 stages = 96KB
#define ST_BH 16384
#define ST_SZ 32768
#define MM_SMEM (3 * ST_SZ)

template <int EPI>
__global__ __launch_bounds__(256, 2) void mm(GArgs g) {
    extern __shared__ char smem[];
    const u32 sb = smem_u32(smem);
    __shared__ int rows[128];
    const int tid = threadIdx.x, lane = tid & 31, wid = tid >> 5;
    const int e = blockIdx.z, n0 = blockIdx.x * 128, m0 = blockIdx.y * 128;

    if (tid < 128) rows[tid] = (g.gids && EPI != 2) ? g.gids[e * g.cap + m0 + tid] : (m0 + tid);
    __syncthreads();

    // loads: thread -> row tid>>1, half (tid&1)*64B, 4x16B per tensor
    const int ra = tid >> 1, ha = tid & 1;
    const char* pAh = g.Ah + ((size_t)e * g.aStrE + (size_t)rows[ra] * g.K + ha * 32) * 2;
    const char* pBh = g.Bh + ((size_t)e * g.bStrE + (size_t)(n0 + ra) * g.K + ha * 32) * 2;
    u32 dstA[4];
#pragma unroll
    for (int i = 0; i < 4; i++) {
        u32 o = ra * 128 + ha * 64 + i * 16;
        dstA[i] = o ^ ((o >> 3) & 0x70);
    }

    // warp tile 32(M) x 64(N): wm = (wid>>1)*32, wn = (wid&1)*64
    const int wm = (wid >> 1) * 32, wn = (wid & 1) * 64;
    const u32 xv = (lane & 7) << 4;
    const u32 hib = (lane >> 4) * 16;
    u32 aoffs[2], boffs[4];
#pragma unroll
    for (int mi = 0; mi < 2; mi++) aoffs[mi] = (wm + mi * 16 + (lane & 15)) * 128;
#pragma unroll
    for (int nj = 0; nj < 4; nj++) boffs[nj] = (wn + nj * 16 + (lane & 15)) * 128;

    float acc[2][8][4];
#pragma unroll
    for (int a = 0; a < 2; a++)
#pragma unroll
        for (int b = 0; b < 8; b++)
#pragma unroll
            for (int c = 0; c < 4; c++) acc[a][b][c] = 0.f;

    auto load_stage = [&](int s, int kt) {
        u32 st = sb + s * ST_SZ;
        size_t kb = (size_t)kt * 128;
#pragma unroll
        for (int i = 0; i < 4; i++) {
            cpa16(st + dstA[i],         pAh + kb + i * 16);
            cpa16(st + ST_BH + dstA[i], pBh + kb + i * 16);
        }
    };

    const int NT = g.K >> 6;
    load_stage(0, 0); CP_COMMIT();
    if (NT > 1) { load_stage(1, 1); CP_COMMIT(); }

    for (int kt = 0; kt < NT; kt++) {
        if (kt + 2 < NT) { load_stage((kt + 2) % 3, kt + 2); CP_COMMIT(); CP_WAIT2(); }
        else if (kt + 1 < NT) CP_WAIT1();
        else CP_WAIT0();
        __syncthreads();
        const u32 stb = sb + (kt % 3) * ST_SZ;
#pragma unroll
        for (int ks = 0; ks < 4; ks++) {
            const u32 kx = ks * 32 + hib;
            u32 ah[2][4], bf[4][4];
#pragma unroll
            for (int mi = 0; mi < 2; mi++)
                LDM4(ah[mi], stb + aoffs[mi] + (kx ^ xv));
#pragma unroll
            for (int nj = 0; nj < 4; nj++)
                LDM4(bf[nj], stb + ST_BH + boffs[nj] + (kx ^ xv));
#pragma unroll
            for (int mi = 0; mi < 2; mi++)
#pragma unroll
                for (int nj = 0; nj < 4; nj++)
#pragma unroll
                    for (int o = 0; o < 2; o++)
                        MMA(acc[mi][nj * 2 + o], ah[mi], bf[nj][o], bf[nj][2 + o]);
        }
        __syncthreads();
    }

    // ---------------- epilogue ----------------
    const float* bias = g.bias ? g.bias + (size_t)e * g.biasStrE : nullptr;
#pragma unroll
    for (int mi = 0; mi < 2; mi++)
#pragma unroll
        for (int ni = 0; ni < 8; ni++) {
            const int lr = wm + mi * 16 + (lane >> 2);
            const int col = wn + ni * 8 + (lane & 3) * 2;
            const int n = n0 + col;
            float b0 = 0.f, b1 = 0.f;
            if (bias) { b0 = bias[n]; b1 = bias[n + 1]; }
            float v[4] = {acc[mi][ni][0] + b0, acc[mi][ni][1] + b1,
                          acc[mi][ni][2] + b0, acc[mi][ni][3] + b1};
            if (EPI == 2) {
#pragma unroll
                for (int hrow = 0; hrow < 2; hrow++) {
                    int sl = e * g.cap + m0 + lr + hrow * 8;
                    int tok = g.gids[sl];
                    float sc = g.tsc[sl];
                    float* orow = g.oF + (size_t)tok * DIM + n;
                    atomicAdd(orow,     v[2 * hrow]     * sc);
                    atomicAdd(orow + 1, v[2 * hrow + 1] * sc);
                }
            } else if (EPI == 3) {
                size_t off = (size_t)(m0 + lr) * g.ldo + n;
                g.oF[off] = v[0]; g.oF[off + 1] = v[1];
                g.oF[off + 8 * g.ldo] = v[2]; g.oF[off + 8 * g.ldo + 1] = v[3];
            } else {
#pragma unroll
                for (int hrow = 0; hrow < 2; hrow++) {
                    size_t off = (size_t)e * g.oStrE + (size_t)(m0 + lr + hrow * 8) * g.ldo + n;
                    float v0 = v[2 * hrow], v1 = v[2 * hrow + 1];
                    if (EPI == 0) {
                        v0 = siluf_(v0); v1 = siluf_(v1);
                        u32 h, l;
                        splith2(v0, v1, h, l);
                        *(u32*)(g.oH + off * 2) = h;
                        *(u32*)(g.oL + off * 2) = l;
                    } else {
                        size_t aoff = ((size_t)e * g.auxStrE +
                                       (size_t)(m0 + lr + hrow * 8) * g.ldo + n) * 2;
                        float2 xh = unpackh2(*(const u32*)(g.auxH + aoff));
                        float2 xl = unpackh2(*(const u32*)(g.auxL + aoff));
                        v0 *= (xh.x + xl.x);
                        v1 *= (xh.y + xl.y);
                        *(u32*)(g.oH + off * 2) = packh2(v0, v1);
                    }
                }
            }
        }
}

// ---------------- launch ----------------
extern "C" void kernel_launch(void* const* d_in, const int* in_sizes, int n_in,
                              void* d_out, int out_size) {
    const float* x      = (const float*)d_in[0];
    const float* gate_w = (const float*)d_in[1];
    const float* up_w   = (const float*)d_in[2];
    const float* up_b   = (const float*)d_in[3];
    const float* gw     = (const float*)d_in[4];
    const float* gb     = (const float*)d_in[5];
    const float* down_w = (const float*)d_in[6];
    const float* down_b = (const float*)d_in[7];
    const float* shg    = (const float*)d_in[8];
    const float* shu    = (const float*)d_in[9];
    const float* shd    = (const float*)d_in[10];
    (void)n_in; (void)out_size;
    float* out = (float*)d_out;

    int T = in_sizes[0] / DIM;               // 8192
    int cap = (T * 2 + NEXP - 1) / NEXP;     // 1024

    unsigned char* buf;
    cudaGetSymbolAddress((void**)&buf, g_buf);
    float* scoresT = (float*)(buf + O_SC);
    int*   ids     = (int*)(buf + O_IDS);
    float* tsc     = (float*)(buf + O_TSC);

    static bool s_init = false;
    if (!s_init) {
        s_init = true;
        cudaFuncSetAttribute(topk_kernel, cudaFuncAttributeMaxDynamicSharedMemorySize,
                             NSORT * (int)sizeof(u64));
        cudaFuncSetAttribute(mm<0>, cudaFuncAttributeMaxDynamicSharedMemorySize, MM_SMEM);
        cudaFuncSetAttribute(mm<1>, cudaFuncAttributeMaxDynamicSharedMemorySize, MM_SMEM);
        cudaFuncSetAttribute(mm<2>, cudaFuncAttributeMaxDynamicSharedMemorySize, MM_SMEM);
        cudaFuncSetAttribute(mm<3>, cudaFuncAttributeMaxDynamicSharedMemorySize, MM_SMEM);
    }

    long w4 = (long)((size_t)NEXP * FDIM * DIM / 4);
    long s4 = (long)((size_t)SHDIM * DIM / 4);

    // ordered so the 6th launch (ncu -s 5 -c 1) is an mm kernel
    cvtk<<<1024, 256>>>((const float4*)x, (uint2*)(buf + O_X),
                        (long)((size_t)T * DIM / 4));                            // 1
    gate_kernel<<<(T + 7) / 8, 256>>>(x, gate_w, scoresT, T);                    // 2
    topk_kernel<<<NEXP, 1024, NSORT * (int)sizeof(u64)>>>(scoresT, ids, tsc, T, cap); // 3
    cvtk<<<512, 256>>>((const float4*)shg, (uint2*)(buf + O_SG), s4);            // 4
    cvtk<<<512, 256>>>((const float4*)shu, (uint2*)(buf + O_SU), s4);            // 5

    GArgs a{};
    // 6) shared gate: silu(x@shg^T) -> SSH/SSL        <-- profiled launch
    a = GArgs{};
    a.Ah = (char*)(buf + O_X); a.aStrE = 0; a.K = DIM;
    a.Bh = (char*)(buf + O_SG); a.bStrE = 0;
    a.oH = (char*)(buf + O_SSH); a.oL = (char*)(buf + O_SSL); a.oStrE = 0; a.ldo = SHDIM;
    mm<0><<<dim3(SHDIM / 128, T / 128, 1), 256, MM_SMEM>>>(a);

    cvtk<<<512, 256>>>((const float4*)shd, (uint2*)(buf + O_SD), s4);            // 7

    // 8) shared up: (x@shu^T) * silu -> SAH (single fp16)
    a.Bh = (char*)(buf + O_SU);
    a.auxH = (char*)(buf + O_SSH); a.auxL = (char*)(buf + O_SSL); a.auxStrE = 0;
    a.oH = (char*)(buf + O_SAH); a.oL = nullptr;
    mm<1><<<dim3(SHDIM / 128, T / 128, 1), 256, MM_SMEM>>>(a);

    // 9) shared down -> out (plain f32 store initializes out)
    a = GArgs{};
    a.Ah = (char*)(buf + O_SAH); a.aStrE = 0; a.K = SHDIM;
    a.Bh = (char*)(buf + O_SD); a.bStrE = 0;
    a.oF = out; a.ldo = DIM;
    mm<3><<<dim3(DIM / 128, T / 128, 1), 256, MM_SMEM>>>(a);

    cvtk<<<4096, 256>>>((const float4*)gw,   (uint2*)(buf + O_WG), w4);          // 10
    cvtk<<<4096, 256>>>((const float4*)up_w, (uint2*)(buf + O_WU), w4);          // 11

    // 12) expert gate: silu(x[ids]@gw^T + gb) -> EGH/EGL
    a = GArgs{};
    a.Ah = (char*)(buf + O_X); a.aStrE = 0; a.K = DIM;
    a.gids = ids; a.cap = cap;
    a.Bh = (char*)(buf + O_WG); a.bStrE = (long long)FDIM * DIM;
    a.bias = gb; a.biasStrE = FDIM;
    a.oH = (char*)(buf + O_EGH); a.oL = (char*)(buf + O_EGL);
    a.oStrE = (long long)cap * FDIM; a.ldo = FDIM;
    mm<0><<<dim3(FDIM / 128, cap / 128, NEXP), 256, MM_SMEM>>>(a);

    // 13) expert up: (x[ids]@up_w^T + up_b) * silu -> EAH (single fp16)
    a.Bh = (char*)(buf + O_WU);
    a.bias = up_b;
    a.auxH = (char*)(buf + O_EGH); a.auxL = (char*)(buf + O_EGL);
    a.auxStrE = (long long)cap * FDIM;
    a.oH = (char*)(buf + O_EAH); a.oL = nullptr;
    mm<1><<<dim3(FDIM / 128, cap / 128, NEXP), 256, MM_SMEM>>>(a);

    cvtk<<<4096, 256>>>((const float4*)down_w, (uint2*)(buf + O_WD), w4);        // 14

    // 15) expert down + weighted scatter-add
    a = GArgs{};
    a.Ah = (char*)(buf + O_EAH); a.aStrE = (long long)cap * FDIM; a.K = FDIM;
    a.gids = ids; a.cap = cap; a.tsc = tsc;
    a.Bh = (char*)(buf + O_WD); a.bStrE = (long long)DIM * FDIM;
    a.bias = down_b; a.biasStrE = DIM;
    a.oF = out; a.ldo = DIM;
    mm<2><<<dim3(DIM / 128, cap / 128, NEXP), 256, MM_SMEM>>>(a);
}

// round 10
// speedup vs baseline: 4.3900x; 1.0613x over previous
#include <cuda_runtime.h>
#include <cuda_fp16.h>
#include <math.h>
#include <stdint.h>

typedef unsigned int u32;
typedef unsigned long long u64;

#define NEXP 16
#define DIM 1024
#define FDIM 4096
#define SHDIM 2048
#define MAXT 8192
#define NSORT 8192
#define MAXCAP 1024

// ---------------- static scratch (fp16 operands) ----------------
constexpr size_t SZ_X  = (size_t)MAXT * DIM * 2;
constexpr size_t SZ_W  = (size_t)NEXP * FDIM * DIM * 2;
constexpr size_t SZ_SW = (size_t)SHDIM * DIM * 2;
constexpr size_t SZ_EA = (size_t)NEXP * MAXCAP * FDIM * 2;
constexpr size_t SZ_SA = (size_t)MAXT * SHDIM * 2;
constexpr size_t O_X  = 0;
constexpr size_t O_WG = O_X + SZ_X,     O_WU = O_WG + SZ_W;
constexpr size_t O_WD = O_WU + SZ_W;
constexpr size_t O_SG = O_WD + SZ_W,    O_SU = O_SG + SZ_SW;
constexpr size_t O_SD = O_SU + SZ_SW;
constexpr size_t O_EGH = O_SD + SZ_SW,  O_EGL = O_EGH + SZ_EA;  // expert silu(gate) hi/lo
constexpr size_t O_EAH = O_EGL + SZ_EA;                          // expert act (single)
constexpr size_t O_SSH = O_EAH + SZ_EA, O_SSL = O_SSH + SZ_SA;  // shared silu(gate) hi/lo
constexpr size_t O_SAH = O_SSL + SZ_SA;                          // shared act (single)
constexpr size_t O_SC  = O_SAH + SZ_SA;
constexpr size_t O_IDS = O_SC + (size_t)NEXP * MAXT * 4;
constexpr size_t O_TSC = O_IDS + (size_t)NEXP * MAXCAP * 4;
constexpr size_t TOTAL = O_TSC + (size_t)NEXP * MAXCAP * 4;
__device__ __align__(1024) unsigned char g_buf[TOTAL];

// ---------------- helpers ----------------
__device__ __forceinline__ u32 smem_u32(const void* p) {
    u32 a;
    asm("{ .reg .u64 t; cvta.to.shared.u64 t, %1; cvt.u32.u64 %0, t; }" : "=r"(a) : "l"(p));
    return a;
}
__device__ __forceinline__ void cpa16(u32 dst, const void* src) {
    asm volatile("cp.async.cg.shared.global [%0], [%1], 16;" :: "r"(dst), "l"(src) : "memory");
}
#define CP_COMMIT() asm volatile("cp.async.commit_group;" ::: "memory")
#define CP_WAIT2()  asm volatile("cp.async.wait_group 2;" ::: "memory")
#define CP_WAIT1()  asm volatile("cp.async.wait_group 1;" ::: "memory")
#define CP_WAIT0()  asm volatile("cp.async.wait_group 0;" ::: "memory")
#define LDM4(R, a) \
    asm volatile("ldmatrix.sync.aligned.m8n8.x4.shared.b16 {%0,%1,%2,%3}, [%4];" \
        : "=r"((R)[0]), "=r"((R)[1]), "=r"((R)[2]), "=r"((R)[3]) : "r"(a))
#define MMA(c, A, b0, b1) \
    asm volatile("mma.sync.aligned.m16n8k16.row.col.f32.f16.f16.f32 " \
        "{%0,%1,%2,%3}, {%4,%5,%6,%7}, {%8,%9}, {%0,%1,%2,%3};" \
        : "+f"((c)[0]), "+f"((c)[1]), "+f"((c)[2]), "+f"((c)[3]) \
        : "r"((A)[0]), "r"((A)[1]), "r"((A)[2]), "r"((A)[3]), "r"(b0), "r"(b1))

__device__ __forceinline__ u32 packh2(float a, float b) {
    __half2 h = __floats2half2_rn(a, b);
    return *reinterpret_cast<u32*>(&h);
}
__device__ __forceinline__ float2 unpackh2(u32 v) {
    __half2 h = *reinterpret_cast<__half2*>(&v);
    return __half22float2(h);
}
__device__ __forceinline__ void splith2(float a, float b, u32& h, u32& l) {
    h = packh2(a, b);
    float2 f = unpackh2(h);
    l = packh2(a - f.x, b - f.y);
}
__device__ __forceinline__ float sigmoidf_(float x) { return 1.f / (1.f + expf(-x)); }
__device__ __forceinline__ float siluf_(float x)    { return __fdividef(x, 1.f + __expf(-x)); }

// ---------------- fp32 -> fp16 convert ----------------
__global__ void cvtk(const float4* __restrict__ in, uint2* __restrict__ oh, long n4) {
    long i = blockIdx.x * (long)blockDim.x + threadIdx.x;
    long st = (long)gridDim.x * blockDim.x;
    for (; i < n4; i += st) {
        float4 q = in[i];
        oh[i] = make_uint2(packh2(q.x, q.y), packh2(q.z, q.w));
    }
}

// ---------------- gate scores (exact fp32 for stable ranking) ----------------
__global__ void gate_kernel(const float* __restrict__ h, const float* __restrict__ gate_w,
                            float* __restrict__ scoresT, int T) {
    int warp = (int)((blockIdx.x * blockDim.x + threadIdx.x) >> 5);
    int lane = threadIdx.x & 31;
    if (warp >= T) return;
    const float* hr = h + (size_t)warp * DIM;
    float hreg[32];
#pragma unroll
    for (int i = 0; i < 32; i++) hreg[i] = hr[lane + 32 * i];
#pragma unroll
    for (int e = 0; e < NEXP; e++) {
        const float* w = gate_w + e * DIM;
        float s = 0.f;
#pragma unroll
        for (int i = 0; i < 32; i++) s = fmaf(hreg[i], w[lane + 32 * i], s);
#pragma unroll
        for (int o = 16; o; o >>= 1) s += __shfl_xor_sync(0xffffffffu, s, o);
        if (lane == 0) scoresT[e * T + warp] = sigmoidf_(s);
    }
}

// ---------------- exact top-k (matches jax.lax.top_k ties) ----------------
__global__ void topk_kernel(const float* __restrict__ scoresT, int* __restrict__ ids,
                            float* __restrict__ tscore, int T, int cap) {
    extern __shared__ u64 s_keys[];
    int e = blockIdx.x;
    const float* s = scoresT + (size_t)e * T;
    for (int i = threadIdx.x; i < NSORT; i += blockDim.x) {
        float v = (i < T) ? s[i] : -1e30f;
        u32 u = __float_as_uint(v);
        u32 ob = (u & 0x80000000u) ? ~u : (u | 0x80000000u);
        s_keys[i] = ((u64)ob << 32) | (u32)(0xFFFFFFFFu - (u32)i);
    }
    __syncthreads();
    for (u32 k = 2; k <= NSORT; k <<= 1)
        for (u32 j = k >> 1; j > 0; j >>= 1) {
            for (u32 i = threadIdx.x; i < NSORT; i += blockDim.x) {
                u32 ixj = i ^ j;
                if (ixj > i) {
                    u64 a = s_keys[i], b = s_keys[ixj];
                    if (((i & k) == 0) ? (a < b) : (a > b)) { s_keys[i] = b; s_keys[ixj] = a; }
                }
            }
            __syncthreads();
        }
    for (int i = threadIdx.x; i < cap; i += blockDim.x) {
        u32 idx = 0xFFFFFFFFu - (u32)(s_keys[i] & 0xFFFFFFFFull);
        ids[e * cap + i] = (int)idx;
        tscore[e * cap + i] = s[idx];
    }
}

// ========== tensor-core GEMM: C = A@B^T, single-term fp16 ==========
// CTA tile 128x128, BK=64, 3-stage cp.async, 2 CTAs/SM (96KB smem).
// EPI 0: silu(acc+bias) -> fp16 hi/lo  (exact pair for later GLU multiply)
//     1: (acc+bias)*(auxH+auxL) -> fp16 single
//     2: atomicAdd(out[tok], (acc+bias)*score)
//     3: plain f32 store
struct GArgs {
    const char* Ah; long long aStrE; int K;
    const int* gids; int cap;
    const char* Bh; long long bStrE;
    const float* bias; long long biasStrE;
    const char* auxH; const char* auxL; long long auxStrE;
    char* oH; char* oL; long long oStrE; int ldo;
    float* oF;
    const float* tsc;
};

// stage: Ah 16KB | Bh 16KB = 32KB; 3 stages = 96KB
#define ST_BH 16384
#define ST_SZ 32768
#define MM_SMEM (3 * ST_SZ)

template <int EPI>
__global__ __launch_bounds__(256, 2) void mm(GArgs g) {
    extern __shared__ char smem[];
    const u32 sb = smem_u32(smem);
    __shared__ int rows[128];
    const int tid = threadIdx.x, lane = tid & 31, wid = tid >> 5;
    const int e = blockIdx.z, n0 = blockIdx.x * 128, m0 = blockIdx.y * 128;

    if (tid < 128) rows[tid] = (g.gids && EPI != 2) ? g.gids[e * g.cap + m0 + tid] : (m0 + tid);
    __syncthreads();

    const int ra = tid >> 1, ha = tid & 1;
    const char* pAh = g.Ah + ((size_t)e * g.aStrE + (size_t)rows[ra] * g.K + ha * 32) * 2;
    const char* pBh = g.Bh + ((size_t)e * g.bStrE + (size_t)(n0 + ra) * g.K + ha * 32) * 2;
    u32 dstA[4];
#pragma unroll
    for (int i = 0; i < 4; i++) {
        u32 o = ra * 128 + ha * 64 + i * 16;
        dstA[i] = o ^ ((o >> 3) & 0x70);
    }

    const int wm = (wid >> 1) * 32, wn = (wid & 1) * 64;
    const u32 xv = (lane & 7) << 4;
    const u32 hib = (lane >> 4) * 16;
    u32 aoffs[2], boffs[4];
#pragma unroll
    for (int mi = 0; mi < 2; mi++) aoffs[mi] = (wm + mi * 16 + (lane & 15)) * 128;
#pragma unroll
    for (int nj = 0; nj < 4; nj++) boffs[nj] = (wn + nj * 16 + (lane & 15)) * 128;

    float acc[2][8][4];
#pragma unroll
    for (int a = 0; a < 2; a++)
#pragma unroll
        for (int b = 0; b < 8; b++)
#pragma unroll
            for (int c = 0; c < 4; c++) acc[a][b][c] = 0.f;

    auto load_stage = [&](int s, int kt) {
        u32 st = sb + s * ST_SZ;
        size_t kb = (size_t)kt * 128;
#pragma unroll
        for (int i = 0; i < 4; i++) {
            cpa16(st + dstA[i],         pAh + kb + i * 16);
            cpa16(st + ST_BH + dstA[i], pBh + kb + i * 16);
        }
    };

    const int NT = g.K >> 6;
    load_stage(0, 0); CP_COMMIT();
    if (NT > 1) { load_stage(1, 1); CP_COMMIT(); }

    for (int kt = 0; kt < NT; kt++) {
        if (kt + 2 < NT) { load_stage((kt + 2) % 3, kt + 2); CP_COMMIT(); CP_WAIT2(); }
        else if (kt + 1 < NT) CP_WAIT1();
        else CP_WAIT0();
        __syncthreads();
        const u32 stb = sb + (kt % 3) * ST_SZ;
#pragma unroll
        for (int ks = 0; ks < 4; ks++) {
            const u32 kx = ks * 32 + hib;
            u32 ah[2][4], bf[4][4];
#pragma unroll
            for (int mi = 0; mi < 2; mi++)
                LDM4(ah[mi], stb + aoffs[mi] + (kx ^ xv));
#pragma unroll
            for (int nj = 0; nj < 4; nj++)
                LDM4(bf[nj], stb + ST_BH + boffs[nj] + (kx ^ xv));
#pragma unroll
            for (int mi = 0; mi < 2; mi++)
#pragma unroll
                for (int nj = 0; nj < 4; nj++)
#pragma unroll
                    for (int o = 0; o < 2; o++)
                        MMA(acc[mi][nj * 2 + o], ah[mi], bf[nj][o], bf[nj][2 + o]);
        }
        __syncthreads();
    }

    // ---------------- epilogue ----------------
    const float* bias = g.bias ? g.bias + (size_t)e * g.biasStrE : nullptr;
#pragma unroll
    for (int mi = 0; mi < 2; mi++)
#pragma unroll
        for (int ni = 0; ni < 8; ni++) {
            const int lr = wm + mi * 16 + (lane >> 2);
            const int col = wn + ni * 8 + (lane & 3) * 2;
            const int n = n0 + col;
            float b0 = 0.f, b1 = 0.f;
            if (bias) { b0 = bias[n]; b1 = bias[n + 1]; }
            float v[4] = {acc[mi][ni][0] + b0, acc[mi][ni][1] + b1,
                          acc[mi][ni][2] + b0, acc[mi][ni][3] + b1};
            if (EPI == 2) {
#pragma unroll
                for (int hrow = 0; hrow < 2; hrow++) {
                    int sl = e * g.cap + m0 + lr + hrow * 8;
                    int tok = g.gids[sl];
                    float sc = g.tsc[sl];
                    float* orow = g.oF + (size_t)tok * DIM + n;
                    atomicAdd(orow,     v[2 * hrow]     * sc);
                    atomicAdd(orow + 1, v[2 * hrow + 1] * sc);
                }
            } else if (EPI == 3) {
                size_t off = (size_t)(m0 + lr) * g.ldo + n;
                g.oF[off] = v[0]; g.oF[off + 1] = v[1];
                g.oF[off + 8 * g.ldo] = v[2]; g.oF[off + 8 * g.ldo + 1] = v[3];
            } else {
#pragma unroll
                for (int hrow = 0; hrow < 2; hrow++) {
                    size_t off = (size_t)e * g.oStrE + (size_t)(m0 + lr + hrow * 8) * g.ldo + n;
                    float v0 = v[2 * hrow], v1 = v[2 * hrow + 1];
                    if (EPI == 0) {
                        v0 = siluf_(v0); v1 = siluf_(v1);
                        u32 h, l;
                        splith2(v0, v1, h, l);
                        *(u32*)(g.oH + off * 2) = h;
                        *(u32*)(g.oL + off * 2) = l;
                    } else {
                        size_t aoff = ((size_t)e * g.auxStrE +
                                       (size_t)(m0 + lr + hrow * 8) * g.ldo + n) * 2;
                        float2 xh = unpackh2(*(const u32*)(g.auxH + aoff));
                        float2 xl = unpackh2(*(const u32*)(g.auxL + aoff));
                        v0 *= (xh.x + xl.x);
                        v1 *= (xh.y + xl.y);
                        *(u32*)(g.oH + off * 2) = packh2(v0, v1);
                    }
                }
            }
        }
}

// ---------------- launch (multi-stream fork/join inside the graph) ----------------
extern "C" void kernel_launch(void* const* d_in, const int* in_sizes, int n_in,
                              void* d_out, int out_size) {
    const float* x      = (const float*)d_in[0];
    const float* gate_w = (const float*)d_in[1];
    const float* up_w   = (const float*)d_in[2];
    const float* up_b   = (const float*)d_in[3];
    const float* gw     = (const float*)d_in[4];
    const float* gb     = (const float*)d_in[5];
    const float* down_w = (const float*)d_in[6];
    const float* down_b = (const float*)d_in[7];
    const float* shg    = (const float*)d_in[8];
    const float* shu    = (const float*)d_in[9];
    const float* shd    = (const float*)d_in[10];
    (void)n_in; (void)out_size;
    float* out = (float*)d_out;

    int T = in_sizes[0] / DIM;               // 8192
    int cap = (T * 2 + NEXP - 1) / NEXP;     // 1024

    unsigned char* buf;
    cudaGetSymbolAddress((void**)&buf, g_buf);
    float* scoresT = (float*)(buf + O_SC);
    int*   ids     = (int*)(buf + O_IDS);
    float* tsc     = (float*)(buf + O_TSC);

    static cudaStream_t s1, s2;
    static cudaEvent_t ev0, evShw, evEw, evS1;
    static bool s_init = false;
    if (!s_init) {
        s_init = true;
        cudaFuncSetAttribute(topk_kernel, cudaFuncAttributeMaxDynamicSharedMemorySize,
                             NSORT * (int)sizeof(u64));
        cudaFuncSetAttribute(mm<0>, cudaFuncAttributeMaxDynamicSharedMemorySize, MM_SMEM);
        cudaFuncSetAttribute(mm<1>, cudaFuncAttributeMaxDynamicSharedMemorySize, MM_SMEM);
        cudaFuncSetAttribute(mm<2>, cudaFuncAttributeMaxDynamicSharedMemorySize, MM_SMEM);
        cudaFuncSetAttribute(mm<3>, cudaFuncAttributeMaxDynamicSharedMemorySize, MM_SMEM);
        cudaStreamCreateWithFlags(&s1, cudaStreamNonBlocking);
        cudaStreamCreateWithFlags(&s2, cudaStreamNonBlocking);
        cudaEventCreateWithFlags(&ev0,  cudaEventDisableTiming);
        cudaEventCreateWithFlags(&evShw, cudaEventDisableTiming);
        cudaEventCreateWithFlags(&evEw, cudaEventDisableTiming);
        cudaEventCreateWithFlags(&evS1, cudaEventDisableTiming);
    }

    long w4 = (long)((size_t)NEXP * FDIM * DIM / 4);
    long s4 = (long)((size_t)SHDIM * DIM / 4);

    // fork s1 (routing) and s2 (weight conversions) off the capture stream
    cudaEventRecord(ev0, 0);
    cudaStreamWaitEvent(s1, ev0, 0);
    cudaStreamWaitEvent(s2, ev0, 0);

    // main: x -> fp16 (needed by shared + expert GEMMs)
    cvtk<<<1024, 256>>>((const float4*)x, (uint2*)(buf + O_X),
                        (long)((size_t)T * DIM / 4));                            // L1

    // s1: gate scores + exact top-k
    gate_kernel<<<(T + 7) / 8, 256, 0, s1>>>(x, gate_w, scoresT, T);             // L2
    topk_kernel<<<NEXP, 1024, NSORT * (int)sizeof(u64), s1>>>(scoresT, ids, tsc, T, cap); // L3
    cudaEventRecord(evS1, s1);

    // s2: shared weights first (unblock main), then expert weights
    cvtk<<<512, 256, 0, s2>>>((const float4*)shg, (uint2*)(buf + O_SG), s4);     // L4
    cvtk<<<512, 256, 0, s2>>>((const float4*)shu, (uint2*)(buf + O_SU), s4);     // L5
    cudaEventRecord(evShw, s2);
    cudaStreamWaitEvent(0, evShw, 0);

    GArgs a{};
    // L6 (profiled): shared gate: silu(x@shg^T) -> SSH/SSL
    a = GArgs{};
    a.Ah = (char*)(buf + O_X); a.aStrE = 0; a.K = DIM;
    a.Bh = (char*)(buf + O_SG); a.bStrE = 0;
    a.oH = (char*)(buf + O_SSH); a.oL = (char*)(buf + O_SSL); a.oStrE = 0; a.ldo = SHDIM;
    mm<0><<<dim3(SHDIM / 128, T / 128, 1), 256, MM_SMEM>>>(a);

    // s2 continues under the shared GEMMs
    cvtk<<<512, 256, 0, s2>>>((const float4*)shd, (uint2*)(buf + O_SD), s4);
    cvtk<<<4096, 256, 0, s2>>>((const float4*)gw,     (uint2*)(buf + O_WG), w4);
    cvtk<<<4096, 256, 0, s2>>>((const float4*)up_w,   (uint2*)(buf + O_WU), w4);
    cvtk<<<4096, 256, 0, s2>>>((const float4*)down_w, (uint2*)(buf + O_WD), w4);
    cudaEventRecord(evEw, s2);

    // shared up: (x@shu^T) * silu -> SAH (single fp16)
    a.Bh = (char*)(buf + O_SU);
    a.auxH = (char*)(buf + O_SSH); a.auxL = (char*)(buf + O_SSL); a.auxStrE = 0;
    a.oH = (char*)(buf + O_SAH); a.oL = nullptr;
    mm<1><<<dim3(SHDIM / 128, T / 128, 1), 256, MM_SMEM>>>(a);

    // shared down -> out (plain f32 store initializes out); needs shd cvt (in evEw)
    cudaStreamWaitEvent(0, evEw, 0);
    a = GArgs{};
    a.Ah = (char*)(buf + O_SAH); a.aStrE = 0; a.K = SHDIM;
    a.Bh = (char*)(buf + O_SD); a.bStrE = 0;
    a.oF = out; a.ldo = DIM;
    mm<3><<<dim3(DIM / 128, T / 128, 1), 256, MM_SMEM>>>(a);

    // join routing stream before expert chain
    cudaStreamWaitEvent(0, evS1, 0);

    // expert gate: silu(x[ids]@gw^T + gb) -> EGH/EGL
    a = GArgs{};
    a.Ah = (char*)(buf + O_X); a.aStrE = 0; a.K = DIM;
    a.gids = ids; a.cap = cap;
    a.Bh = (char*)(buf + O_WG); a.bStrE = (long long)FDIM * DIM;
    a.bias = gb; a.biasStrE = FDIM;
    a.oH = (char*)(buf + O_EGH); a.oL = (char*)(buf + O_EGL);
    a.oStrE = (long long)cap * FDIM; a.ldo = FDIM;
    mm<0><<<dim3(FDIM / 128, cap / 128, NEXP), 256, MM_SMEM>>>(a);

    // expert up: (x[ids]@up_w^T + up_b) * silu -> EAH (single fp16)
    a.Bh = (char*)(buf + O_WU);
    a.bias = up_b;
    a.auxH = (char*)(buf + O_EGH); a.auxL = (char*)(buf + O_EGL);
    a.auxStrE = (long long)cap * FDIM;
    a.oH = (char*)(buf + O_EAH); a.oL = nullptr;
    mm<1><<<dim3(FDIM / 128, cap / 128, NEXP), 256, MM_SMEM>>>(a);

    // expert down + weighted scatter-add
    a = GArgs{};
    a.Ah = (char*)(buf + O_EAH); a.aStrE = (long long)cap * FDIM; a.K = FDIM;
    a.gids = ids; a.cap = cap; a.tsc = tsc;
    a.Bh = (char*)(buf + O_WD); a.bStrE = (long long)DIM * FDIM;
    a.bias = down_b; a.biasStrE = DIM;
    a.oF = out; a.ldo = DIM;
    mm<2><<<dim3(DIM / 128, cap / 128, NEXP), 256, MM_SMEM>>>(a);
}

// round 11
// speedup vs baseline: 5.1995x; 1.1844x over previous
#include <cuda_runtime.h>
#include <cuda_fp16.h>
#include <math.h>
#include <stdint.h>

typedef unsigned int u32;
typedef unsigned long long u64;

#define NEXP 16
#define DIM 1024
#define FDIM 4096
#define SHDIM 2048
#define MAXT 8192
#define NSORT 8192
#define MAXCAP 1024

// ---------------- static scratch (fp16 operands) ----------------
constexpr size_t SZ_X  = (size_t)MAXT * DIM * 2;
constexpr size_t SZ_W  = (size_t)NEXP * FDIM * DIM * 2;
constexpr size_t SZ_SW = (size_t)SHDIM * DIM * 2;
constexpr size_t SZ_EA = (size_t)NEXP * MAXCAP * FDIM * 2;
constexpr size_t SZ_SA = (size_t)MAXT * SHDIM * 2;
constexpr size_t O_X  = 0;
constexpr size_t O_WG = O_X + SZ_X,     O_WU = O_WG + SZ_W;
constexpr size_t O_WD = O_WU + SZ_W;
constexpr size_t O_SG = O_WD + SZ_W,    O_SU = O_SG + SZ_SW;
constexpr size_t O_SD = O_SU + SZ_SW;
constexpr size_t O_EA = O_SD + SZ_SW;                    // expert act (single fp16)
constexpr size_t O_SA = O_EA + SZ_EA;                    // shared act (single fp16)
constexpr size_t O_SC  = O_SA + SZ_SA;
constexpr size_t O_IDS = O_SC + (size_t)NEXP * MAXT * 4;
constexpr size_t O_TSC = O_IDS + (size_t)NEXP * MAXCAP * 4;
constexpr size_t TOTAL = O_TSC + (size_t)NEXP * MAXCAP * 4;
__device__ __align__(1024) unsigned char g_buf[TOTAL];

// ---------------- helpers ----------------
__device__ __forceinline__ u32 smem_u32(const void* p) {
    u32 a;
    asm("{ .reg .u64 t; cvta.to.shared.u64 t, %1; cvt.u32.u64 %0, t; }" : "=r"(a) : "l"(p));
    return a;
}
__device__ __forceinline__ void cpa16(u32 dst, const void* src) {
    asm volatile("cp.async.cg.shared.global [%0], [%1], 16;" :: "r"(dst), "l"(src) : "memory");
}
#define CP_COMMIT() asm volatile("cp.async.commit_group;" ::: "memory")
#define CP_WAIT2()  asm volatile("cp.async.wait_group 2;" ::: "memory")
#define CP_WAIT1()  asm volatile("cp.async.wait_group 1;" ::: "memory")
#define CP_WAIT0()  asm volatile("cp.async.wait_group 0;" ::: "memory")
#define LDM4(R, a) \
    asm volatile("ldmatrix.sync.aligned.m8n8.x4.shared.b16 {%0,%1,%2,%3}, [%4];" \
        : "=r"((R)[0]), "=r"((R)[1]), "=r"((R)[2]), "=r"((R)[3]) : "r"(a))
#define MMA(c, A, b0, b1) \
    asm volatile("mma.sync.aligned.m16n8k16.row.col.f32.f16.f16.f32 " \
        "{%0,%1,%2,%3}, {%4,%5,%6,%7}, {%8,%9}, {%0,%1,%2,%3};" \
        : "+f"((c)[0]), "+f"((c)[1]), "+f"((c)[2]), "+f"((c)[3]) \
        : "r"((A)[0]), "r"((A)[1]), "r"((A)[2]), "r"((A)[3]), "r"(b0), "r"(b1))

__device__ __forceinline__ u32 packh2(float a, float b) {
    __half2 h = __floats2half2_rn(a, b);
    return *reinterpret_cast<u32*>(&h);
}
__device__ __forceinline__ float sigmoidf_(float x) { return 1.f / (1.f + expf(-x)); }
__device__ __forceinline__ float siluf_(float x)    { return __fdividef(x, 1.f + __expf(-x)); }

// ---------------- fp32 -> fp16 convert ----------------
__global__ void cvtk(const float4* __restrict__ in, uint2* __restrict__ oh, long n4) {
    long i = blockIdx.x * (long)blockDim.x + threadIdx.x;
    long st = (long)gridDim.x * blockDim.x;
    for (; i < n4; i += st) {
        float4 q = in[i];
        oh[i] = make_uint2(packh2(q.x, q.y), packh2(q.z, q.w));
    }
}

// ---------------- gate scores (exact fp32 for stable ranking) ----------------
__global__ void gate_kernel(const float* __restrict__ h, const float* __restrict__ gate_w,
                            float* __restrict__ scoresT, int T) {
    int warp = (int)((blockIdx.x * blockDim.x + threadIdx.x) >> 5);
    int lane = threadIdx.x & 31;
    if (warp >= T) return;
    const float* hr = h + (size_t)warp * DIM;
    float hreg[32];
#pragma unroll
    for (int i = 0; i < 32; i++) hreg[i] = hr[lane + 32 * i];
#pragma unroll
    for (int e = 0; e < NEXP; e++) {
        const float* w = gate_w + e * DIM;
        float s = 0.f;
#pragma unroll
        for (int i = 0; i < 32; i++) s = fmaf(hreg[i], w[lane + 32 * i], s);
#pragma unroll
        for (int o = 16; o; o >>= 1) s += __shfl_xor_sync(0xffffffffu, s, o);
        if (lane == 0) scoresT[e * T + warp] = sigmoidf_(s);
    }
}

// ---------------- exact top-k (matches jax.lax.top_k ties) ----------------
__global__ void topk_kernel(const float* __restrict__ scoresT, int* __restrict__ ids,
                            float* __restrict__ tscore, int T, int cap) {
    extern __shared__ u64 s_keys[];
    int e = blockIdx.x;
    const float* s = scoresT + (size_t)e * T;
    for (int i = threadIdx.x; i < NSORT; i += blockDim.x) {
        float v = (i < T) ? s[i] : -1e30f;
        u32 u = __float_as_uint(v);
        u32 ob = (u & 0x80000000u) ? ~u : (u | 0x80000000u);
        s_keys[i] = ((u64)ob << 32) | (u32)(0xFFFFFFFFu - (u32)i);
    }
    __syncthreads();
    for (u32 k = 2; k <= NSORT; k <<= 1)
        for (u32 j = k >> 1; j > 0; j >>= 1) {
            for (u32 i = threadIdx.x; i < NSORT; i += blockDim.x) {
                u32 ixj = i ^ j;
                if (ixj > i) {
                    u64 a = s_keys[i], b = s_keys[ixj];
                    if (((i & k) == 0) ? (a < b) : (a > b)) { s_keys[i] = b; s_keys[ixj] = a; }
                }
            }
            __syncthreads();
        }
    for (int i = threadIdx.x; i < cap; i += blockDim.x) {
        u32 idx = 0xFFFFFFFFu - (u32)(s_keys[i] & 0xFFFFFFFFull);
        ids[e * cap + i] = (int)idx;
        tscore[e * cap + i] = s[idx];
    }
}

// ========== fused GLU GEMM: out = silu(A@G^T+gb) * (A@U^T+ub), fp16 ==========
// CTA tile 128(M)x64(N), two B tiles. BK=64, 3-stage cp.async, 2 CTAs/SM.
#define G_BG 16384
#define G_BU 24576
#define G_ST 32768
#define GLU_SMEM (3 * G_ST)

template <bool GATHER>
__global__ __launch_bounds__(256, 2) void glu(
    const char* __restrict__ Ah, int K, const int* __restrict__ gids, int cap,
    const char* __restrict__ Bg, const char* __restrict__ Bu, long long bStrE,
    const float* __restrict__ gbias, const float* __restrict__ ubias, long long biasStrE,
    char* __restrict__ oH, long long oStrE, int ldo) {
    extern __shared__ char smem[];
    const u32 sb = smem_u32(smem);
    __shared__ int rows[128];
    const int tid = threadIdx.x, lane = tid & 31, wid = tid >> 5;
    const int e = blockIdx.z, n0 = blockIdx.x * 64, m0 = blockIdx.y * 128;

    if (tid < 128) rows[tid] = GATHER ? gids[e * cap + m0 + tid] : (m0 + tid);
    __syncthreads();

    // A loads: row tid>>1, half (tid&1)*64B, 4x16B
    const int ra = tid >> 1, ha = tid & 1;
    const char* pA = Ah + ((size_t)rows[ra] * K + ha * 32) * 2;
    u32 dstA[4];
#pragma unroll
    for (int i = 0; i < 4; i++) {
        u32 o = ra * 128 + ha * 64 + i * 16;
        dstA[i] = o ^ ((o >> 3) & 0x70);
    }
    // B loads (per tile): row tid>>2 (0..63), quarter (tid&3)*32B, 2x16B
    const int rb = tid >> 2, qb = tid & 3;
    const char* pBg = Bg + ((size_t)e * bStrE + (size_t)(n0 + rb) * K + qb * 16) * 2;
    const char* pBu = Bu + ((size_t)e * bStrE + (size_t)(n0 + rb) * K + qb * 16) * 2;
    u32 dstB[2];
#pragma unroll
    for (int i = 0; i < 2; i++) {
        u32 o = rb * 128 + qb * 32 + i * 16;
        dstB[i] = o ^ ((o >> 3) & 0x70);
    }

    // warp tile 32(M) x 32(N): wm = (wid>>1)*32, wn = (wid&1)*32
    const int wm = (wid >> 1) * 32, wn = (wid & 1) * 32;
    const u32 xv = (lane & 7) << 4;
    const u32 hib = (lane >> 4) * 16;
    u32 aoffs[2], boffs[2];
#pragma unroll
    for (int mi = 0; mi < 2; mi++) aoffs[mi] = (wm + mi * 16 + (lane & 15)) * 128;
#pragma unroll
    for (int nh = 0; nh < 2; nh++) boffs[nh] = (wn + nh * 16 + (lane & 15)) * 128;

    float accG[2][4][4], accU[2][4][4];
#pragma unroll
    for (int a = 0; a < 2; a++)
#pragma unroll
        for (int b = 0; b < 4; b++)
#pragma unroll
            for (int c = 0; c < 4; c++) { accG[a][b][c] = 0.f; accU[a][b][c] = 0.f; }

    auto load_stage = [&](int s, int kt) {
        u32 st = sb + s * G_ST;
        size_t kb = (size_t)kt * 128;
#pragma unroll
        for (int i = 0; i < 4; i++) cpa16(st + dstA[i], pA + kb + i * 16);
#pragma unroll
        for (int i = 0; i < 2; i++) {
            cpa16(st + G_BG + dstB[i], pBg + kb + i * 16);
            cpa16(st + G_BU + dstB[i], pBu + kb + i * 16);
        }
    };

    const int NT = K >> 6;
    load_stage(0, 0); CP_COMMIT();
    if (NT > 1) { load_stage(1, 1); CP_COMMIT(); }

    for (int kt = 0; kt < NT; kt++) {
        if (kt + 2 < NT) { load_stage((kt + 2) % 3, kt + 2); CP_COMMIT(); CP_WAIT2(); }
        else if (kt + 1 < NT) CP_WAIT1();
        else CP_WAIT0();
        __syncthreads();
        const u32 stb = sb + (kt % 3) * G_ST;
#pragma unroll
        for (int ks = 0; ks < 4; ks++) {
            const u32 kx = ks * 32 + hib;
            u32 ah[2][4], bg[2][4], bu[2][4];
#pragma unroll
            for (int mi = 0; mi < 2; mi++)
                LDM4(ah[mi], stb + aoffs[mi] + (kx ^ xv));
#pragma unroll
            for (int nh = 0; nh < 2; nh++) {
                u32 bd = stb + boffs[nh] + (kx ^ xv);
                LDM4(bg[nh], bd + G_BG);
                LDM4(bu[nh], bd + G_BU);
            }
#pragma unroll
            for (int mi = 0; mi < 2; mi++)
#pragma unroll
                for (int nh = 0; nh < 2; nh++)
#pragma unroll
                    for (int o = 0; o < 2; o++) {
                        MMA(accG[mi][nh * 2 + o], ah[mi], bg[nh][o], bg[nh][2 + o]);
                        MMA(accU[mi][nh * 2 + o], ah[mi], bu[nh][o], bu[nh][2 + o]);
                    }
        }
        __syncthreads();
    }

    // epilogue: silu(g+gb)*(u+ub) -> single fp16
    const float* gbp = gbias ? gbias + (size_t)e * biasStrE : nullptr;
    const float* ubp = ubias ? ubias + (size_t)e * biasStrE : nullptr;
#pragma unroll
    for (int mi = 0; mi < 2; mi++)
#pragma unroll
        for (int ni = 0; ni < 4; ni++) {
            const int lr = wm + mi * 16 + (lane >> 2);
            const int n = n0 + wn + ni * 8 + (lane & 3) * 2;
            float gb0 = 0.f, gb1 = 0.f, ub0 = 0.f, ub1 = 0.f;
            if (gbp) { gb0 = gbp[n]; gb1 = gbp[n + 1]; ub0 = ubp[n]; ub1 = ubp[n + 1]; }
#pragma unroll
            for (int hrow = 0; hrow < 2; hrow++) {
                float g0 = accG[mi][ni][2 * hrow]     + gb0;
                float g1 = accG[mi][ni][2 * hrow + 1] + gb1;
                float u0 = accU[mi][ni][2 * hrow]     + ub0;
                float u1 = accU[mi][ni][2 * hrow + 1] + ub1;
                float v0 = siluf_(g0) * u0;
                float v1 = siluf_(g1) * u1;
                size_t off = (size_t)e * oStrE + (size_t)(m0 + lr + hrow * 8) * ldo + n;
                *(u32*)(oH + off * 2) = packh2(v0, v1);
            }
        }
}

// ========== down GEMM: C = A@B^T, single fp16 ==========
// EPI 2: atomicAdd(out[tok], (acc+bias)*score)    3: plain f32 store
struct GArgs {
    const char* Ah; long long aStrE; int K;
    const int* gids; int cap;
    const char* Bh; long long bStrE;
    const float* bias; long long biasStrE;
    float* oF; int ldo;
    const float* tsc;
};
#define ST_BH 16384
#define ST_SZ 32768
#define MM_SMEM (3 * ST_SZ)

template <int EPI>
__global__ __launch_bounds__(256, 2) void mm(GArgs g) {
    extern __shared__ char smem[];
    const u32 sb = smem_u32(smem);
    const int tid = threadIdx.x, lane = tid & 31, wid = tid >> 5;
    const int e = blockIdx.z, n0 = blockIdx.x * 128, m0 = blockIdx.y * 128;

    const int ra = tid >> 1, ha = tid & 1;
    const char* pAh = g.Ah + ((size_t)e * g.aStrE + (size_t)(m0 + ra) * g.K + ha * 32) * 2;
    const char* pBh = g.Bh + ((size_t)e * g.bStrE + (size_t)(n0 + ra) * g.K + ha * 32) * 2;
    u32 dstA[4];
#pragma unroll
    for (int i = 0; i < 4; i++) {
        u32 o = ra * 128 + ha * 64 + i * 16;
        dstA[i] = o ^ ((o >> 3) & 0x70);
    }

    const int wm = (wid >> 1) * 32, wn = (wid & 1) * 64;
    const u32 xv = (lane & 7) << 4;
    const u32 hib = (lane >> 4) * 16;
    u32 aoffs[2], boffs[4];
#pragma unroll
    for (int mi = 0; mi < 2; mi++) aoffs[mi] = (wm + mi * 16 + (lane & 15)) * 128;
#pragma unroll
    for (int nj = 0; nj < 4; nj++) boffs[nj] = (wn + nj * 16 + (lane & 15)) * 128;

    float acc[2][8][4];
#pragma unroll
    for (int a = 0; a < 2; a++)
#pragma unroll
        for (int b = 0; b < 8; b++)
#pragma unroll
            for (int c = 0; c < 4; c++) acc[a][b][c] = 0.f;

    auto load_stage = [&](int s, int kt) {
        u32 st = sb + s * ST_SZ;
        size_t kb = (size_t)kt * 128;
#pragma unroll
        for (int i = 0; i < 4; i++) {
            cpa16(st + dstA[i],         pAh + kb + i * 16);
            cpa16(st + ST_BH + dstA[i], pBh + kb + i * 16);
        }
    };

    const int NT = g.K >> 6;
    load_stage(0, 0); CP_COMMIT();
    if (NT > 1) { load_stage(1, 1); CP_COMMIT(); }

    for (int kt = 0; kt < NT; kt++) {
        if (kt + 2 < NT) { load_stage((kt + 2) % 3, kt + 2); CP_COMMIT(); CP_WAIT2(); }
        else if (kt + 1 < NT) CP_WAIT1();
        else CP_WAIT0();
        __syncthreads();
        const u32 stb = sb + (kt % 3) * ST_SZ;
#pragma unroll
        for (int ks = 0; ks < 4; ks++) {
            const u32 kx = ks * 32 + hib;
            u32 ah[2][4], bf[4][4];
#pragma unroll
            for (int mi = 0; mi < 2; mi++)
                LDM4(ah[mi], stb + aoffs[mi] + (kx ^ xv));
#pragma unroll
            for (int nj = 0; nj < 4; nj++)
                LDM4(bf[nj], stb + ST_BH + boffs[nj] + (kx ^ xv));
#pragma unroll
            for (int mi = 0; mi < 2; mi++)
#pragma unroll
                for (int nj = 0; nj < 4; nj++)
#pragma unroll
                    for (int o = 0; o < 2; o++)
                        MMA(acc[mi][nj * 2 + o], ah[mi], bf[nj][o], bf[nj][2 + o]);
        }
        __syncthreads();
    }

    const float* bias = g.bias ? g.bias + (size_t)e * g.biasStrE : nullptr;
#pragma unroll
    for (int mi = 0; mi < 2; mi++)
#pragma unroll
        for (int ni = 0; ni < 8; ni++) {
            const int lr = wm + mi * 16 + (lane >> 2);
            const int n = n0 + wn + ni * 8 + (lane & 3) * 2;
            float b0 = 0.f, b1 = 0.f;
            if (bias) { b0 = bias[n]; b1 = bias[n + 1]; }
            float v[4] = {acc[mi][ni][0] + b0, acc[mi][ni][1] + b1,
                          acc[mi][ni][2] + b0, acc[mi][ni][3] + b1};
            if (EPI == 2) {
#pragma unroll
                for (int hrow = 0; hrow < 2; hrow++) {
                    int sl = e * g.cap + m0 + lr + hrow * 8;
                    int tok = g.gids[sl];
                    float sc = g.tsc[sl];
                    float* orow = g.oF + (size_t)tok * DIM + n;
                    atomicAdd(orow,     v[2 * hrow]     * sc);
                    atomicAdd(orow + 1, v[2 * hrow + 1] * sc);
                }
            } else {
                size_t off = (size_t)(m0 + lr) * g.ldo + n;
                g.oF[off] = v[0]; g.oF[off + 1] = v[1];
                g.oF[off + 8 * g.ldo] = v[2]; g.oF[off + 8 * g.ldo + 1] = v[3];
            }
        }
}

// ---------------- launch (3-stream fork/join inside the graph) ----------------
extern "C" void kernel_launch(void* const* d_in, const int* in_sizes, int n_in,
                              void* d_out, int out_size) {
    const float* x      = (const float*)d_in[0];
    const float* gate_w = (const float*)d_in[1];
    const float* up_w   = (const float*)d_in[2];
    const float* up_b   = (const float*)d_in[3];
    const float* gw     = (const float*)d_in[4];
    const float* gb     = (const float*)d_in[5];
    const float* down_w = (const float*)d_in[6];
    const float* down_b = (const float*)d_in[7];
    const float* shg    = (const float*)d_in[8];
    const float* shu    = (const float*)d_in[9];
    const float* shd    = (const float*)d_in[10];
    (void)n_in; (void)out_size;
    float* out = (float*)d_out;

    int T = in_sizes[0] / DIM;               // 8192
    int cap = (T * 2 + NEXP - 1) / NEXP;     // 1024

    unsigned char* buf;
    cudaGetSymbolAddress((void**)&buf, g_buf);
    float* scoresT = (float*)(buf + O_SC);
    int*   ids     = (int*)(buf + O_IDS);
    float* tsc     = (float*)(buf + O_TSC);

    static cudaStream_t s1, s2, s3;
    static cudaEvent_t ev0, evX, evS1, evShw, evSDw, evEGw, evDw, evEG;
    static bool s_init = false;
    if (!s_init) {
        s_init = true;
        cudaFuncSetAttribute(topk_kernel, cudaFuncAttributeMaxDynamicSharedMemorySize,
                             NSORT * (int)sizeof(u64));
        cudaFuncSetAttribute(glu<true>,  cudaFuncAttributeMaxDynamicSharedMemorySize, GLU_SMEM);
        cudaFuncSetAttribute(glu<false>, cudaFuncAttributeMaxDynamicSharedMemorySize, GLU_SMEM);
        cudaFuncSetAttribute(mm<2>, cudaFuncAttributeMaxDynamicSharedMemorySize, MM_SMEM);
        cudaFuncSetAttribute(mm<3>, cudaFuncAttributeMaxDynamicSharedMemorySize, MM_SMEM);
        cudaStreamCreateWithFlags(&s1, cudaStreamNonBlocking);
        cudaStreamCreateWithFlags(&s2, cudaStreamNonBlocking);
        cudaStreamCreateWithFlags(&s3, cudaStreamNonBlocking);
        cudaEventCreateWithFlags(&ev0,  cudaEventDisableTiming);
        cudaEventCreateWithFlags(&evX,  cudaEventDisableTiming);
        cudaEventCreateWithFlags(&evS1, cudaEventDisableTiming);
        cudaEventCreateWithFlags(&evShw, cudaEventDisableTiming);
        cudaEventCreateWithFlags(&evSDw, cudaEventDisableTiming);
        cudaEventCreateWithFlags(&evEGw, cudaEventDisableTiming);
        cudaEventCreateWithFlags(&evDw, cudaEventDisableTiming);
        cudaEventCreateWithFlags(&evEG, cudaEventDisableTiming);
    }

    long w4 = (long)((size_t)NEXP * FDIM * DIM / 4);
    long s4 = (long)((size_t)SHDIM * DIM / 4);

    // fork
    cudaEventRecord(ev0, 0);
    cudaStreamWaitEvent(s1, ev0, 0);
    cudaStreamWaitEvent(s2, ev0, 0);

    // main: x -> fp16
    cvtk<<<1024, 256>>>((const float4*)x, (uint2*)(buf + O_X),
                        (long)((size_t)T * DIM / 4));                            // K1
    cudaEventRecord(evX, 0);

    // s1: routing
    gate_kernel<<<(T + 7) / 8, 256, 0, s1>>>(x, gate_w, scoresT, T);             // K2
    topk_kernel<<<NEXP, 1024, NSORT * (int)sizeof(u64), s1>>>(scoresT, ids, tsc, T, cap); // K3
    cudaEventRecord(evS1, s1);

    // s2: weight conversions (shared GLU first, then expert GLU, then downs)
    cvtk<<<512, 256, 0, s2>>>((const float4*)shg, (uint2*)(buf + O_SG), s4);     // K4
    cvtk<<<512, 256, 0, s2>>>((const float4*)shu, (uint2*)(buf + O_SU), s4);     // K5
    cudaEventRecord(evShw, s2);
    cudaStreamWaitEvent(0, evShw, 0);

    // K6 (profiled): shared fused GLU -> SA
    glu<false><<<dim3(SHDIM / 64, T / 128, 1), 256, GLU_SMEM>>>(
        (char*)(buf + O_X), DIM, nullptr, cap,
        (char*)(buf + O_SG), (char*)(buf + O_SU), 0,
        nullptr, nullptr, 0,
        (char*)(buf + O_SA), 0, SHDIM);

    // s2 continues under GEMMs
    cvtk<<<4096, 256, 0, s2>>>((const float4*)gw,   (uint2*)(buf + O_WG), w4);
    cvtk<<<4096, 256, 0, s2>>>((const float4*)up_w, (uint2*)(buf + O_WU), w4);
    cudaEventRecord(evEGw, s2);
    cvtk<<<512, 256, 0, s2>>>((const float4*)shd, (uint2*)(buf + O_SD), s4);
    cudaEventRecord(evSDw, s2);
    cvtk<<<4096, 256, 0, s2>>>((const float4*)down_w, (uint2*)(buf + O_WD), w4);
    cudaEventRecord(evDw, s2);

    // s3: expert fused GLU (overlaps shared chain) -> EA
    cudaStreamWaitEvent(s3, evX, 0);
    cudaStreamWaitEvent(s3, evS1, 0);
    cudaStreamWaitEvent(s3, evEGw, 0);
    glu<true><<<dim3(FDIM / 64, cap / 128, NEXP), 256, GLU_SMEM, s3>>>(
        (char*)(buf + O_X), DIM, ids, cap,
        (char*)(buf + O_WG), (char*)(buf + O_WU), (long long)FDIM * DIM,
        gb, up_b, FDIM,
        (char*)(buf + O_EA), (long long)cap * FDIM, FDIM);
    cudaEventRecord(evEG, s3);

    // main: shared down -> out (plain f32 store initializes out)
    cudaStreamWaitEvent(0, evSDw, 0);
    GArgs a{};
    a.Ah = (char*)(buf + O_SA); a.aStrE = 0; a.K = SHDIM;
    a.Bh = (char*)(buf + O_SD); a.bStrE = 0;
    a.oF = out; a.ldo = DIM;
    mm<3><<<dim3(DIM / 128, T / 128, 1), 256, MM_SMEM>>>(a);

    // main: expert down + weighted scatter-add (after out init + EA + WD)
    cudaStreamWaitEvent(0, evEG, 0);
    cudaStreamWaitEvent(0, evDw, 0);
    a = GArgs{};
    a.Ah = (char*)(buf + O_EA); a.aStrE = (long long)cap * FDIM; a.K = FDIM;
    a.gids = ids; a.cap = cap; a.tsc = tsc;
    a.Bh = (char*)(buf + O_WD); a.bStrE = (long long)DIM * FDIM;
    a.bias = down_b; a.biasStrE = DIM;
    a.oF = out; a.ldo = DIM;
    mm<2><<<dim3(DIM / 128, cap / 128, NEXP), 256, MM_SMEM>>>(a);
}